// round 10
// baseline (speedup 1.0000x reference)
#include <cuda_runtime.h>
#include <cuda_fp16.h>
#include <cstdint>

// Problem constants
constexpr int B_ = 16, T_ = 128, N_ = 64, D_ = 256, H_ = 512;
constexpr int MROWS = B_ * T_ * N_;          // 131072 flattened rows
constexpr int BT   = B_ * T_;                // 2048 attention problems
constexpr size_t BUF  = (size_t)MROWS * H_;  // 67.1M elems (q/k/v buffers)
constexpr size_t XBUF = (size_t)MROWS * D_;  // fp16 copies of x

// ---------------- scratch (device globals) ---------------------------------
__device__ __align__(16) __half g_h[6 * BUF + 2 * XBUF];
// transposed fp16 weights [N=512, K] row-major:
// 6 x (512*256) + (512*1024) + (512*512) = 1,572,864 halves (3 MB)
__device__ __align__(16) __half g_w[1572864];

__device__ __forceinline__ uint32_t pk(float a, float b) {
    __half2 h = __floats2half2_rn(a, b);
    return *reinterpret_cast<uint32_t*>(&h);
}
__device__ __forceinline__ void st2(float* p, float v0, float v1) {
    *reinterpret_cast<float2*>(p) = make_float2(v0, v1);
}
__device__ __forceinline__ void st2(__half* p, float v0, float v1) {
    *reinterpret_cast<__half2*>(p) = __floats2half2_rn(v0, v1);
}

// mma.sync m16n8k16 fp16 in / fp32 accum, D += A*B
__device__ __forceinline__ void mma16(float* d, const uint32_t* a, const uint32_t* b) {
    asm volatile(
        "mma.sync.aligned.m16n8k16.row.col.f32.f16.f16.f32 "
        "{%0,%1,%2,%3}, {%4,%5,%6,%7}, {%8,%9}, {%0,%1,%2,%3};"
        : "+f"(d[0]), "+f"(d[1]), "+f"(d[2]), "+f"(d[3])
        : "r"(a[0]), "r"(a[1]), "r"(a[2]), "r"(a[3]),
          "r"(b[0]), "r"(b[1]));
}

// ldmatrix x4: loads 4 8x8 b16 tiles; lane i (0..15) supplies row addresses,
// lanes 16..31 the +16B column half. Result lane layout = mma fragment layout.
__device__ __forceinline__ void ldsm4(uint32_t* r, uint32_t addr) {
    asm volatile("ldmatrix.sync.aligned.m8n8.x4.shared.b16 {%0,%1,%2,%3}, [%4];"
        : "=r"(r[0]), "=r"(r[1]), "=r"(r[2]), "=r"(r[3]) : "r"(addr));
}

__device__ __forceinline__ void cpa16(uint32_t dst_smem, const void* src) {
    asm volatile("cp.async.cg.shared.global [%0], [%1], 16;" :: "r"(dst_smem), "l"(src));
}
__device__ __forceinline__ void cpa_commit() { asm volatile("cp.async.commit_group;"); }
template<int Ngrp> __device__ __forceinline__ void cpa_wait() {
    asm volatile("cp.async.wait_group %0;" :: "n"(Ngrp));
}

// ======================= conversion pre-pass ==============================
__global__ void cvt_f2h(const float* __restrict__ src, __half* __restrict__ dst, int n4) {
    for (int i = blockIdx.x * blockDim.x + threadIdx.x; i < n4; i += gridDim.x * blockDim.x) {
        float4 v = reinterpret_cast<const float4*>(src)[i];
        reinterpret_cast<uint2*>(dst)[i] = make_uint2(pk(v.x, v.y), pk(v.z, v.w));
    }
}
// Transpose-pack all weights: W[K,512] fp32 -> Wt[512,K] fp16 regions.
struct WSrc { const float* w[8]; };
__global__ void pack_wT(WSrc ws, __half* __restrict__ out) {
    constexpr int R6 = 6 * 131072;            // 786432 (6 x 512*256)
    constexpr int R7 = R6 + 512 * 1024;       // 1310720
    constexpr int TOT = R7 + 512 * 512;       // 1572864
    for (int i = blockIdx.x * blockDim.x + threadIdx.x; i < TOT; i += gridDim.x * blockDim.x) {
        const float* W; int local, K;
        if (i < R6)      { W = ws.w[i / 131072]; local = i % 131072; K = 256; }
        else if (i < R7) { W = ws.w[6];          local = i - R6;     K = 1024; }
        else             { W = ws.w[7];          local = i - R7;     K = 512; }
        int n = local / K, k = local % K;
        out[i] = __float2half_rn(W[(size_t)k * 512 + n]);
    }
}

// =============================== GEMM =====================================
// C[M,512] = act( alpha * (A @ Wt^T) + bias ).  A fp16 [M,K] row-major,
// Wt fp16 [512,K] row-major. Both smem tiles use K-major rows padded to
// 36 words (144 B): rows start on distinct bank groups -> LDSM conflict-free.
// 128x128x64 tiles, 3-slot / 2-ahead cp.async pipeline, 256 thr, 8 warps
// (4m x 2n), fragments via ldmatrix.x4.
constexpr int ROWB = 144;                 // bytes per smem row (36 words)
constexpr int A_BYTES = 128 * ROWB;       // 18432
constexpr int STG_BYTES = 2 * A_BYTES;    // 36864 (A then B)
constexpr int NST = 3;
constexpr size_t GEMM_SMEM = (size_t)STG_BYTES * NST;   // 110592 B

template<typename TC, bool RELU, bool SPLITA, bool PROJ>
__global__ void __launch_bounds__(256, 2) gemm_l(
    const __half* __restrict__ A0, const __half* __restrict__ A1,
    const __half* __restrict__ Wt, const float* __restrict__ bias,
    TC* __restrict__ C, int K, int ksplit, int lda,
    size_t bstride, size_t cstride, float alpha0)
{
    extern __shared__ __align__(1024) uint8_t smem[];
    const uint32_t sb = (uint32_t)__cvta_generic_to_shared(smem);

    const int tid = threadIdx.x, w = tid >> 5, lane = tid & 31;
    const int bm = blockIdx.y * 128;
    const int bn = blockIdx.x * 128;
    const int bz = blockIdx.z;
    const __half* Az = PROJ ? (bz < 3 ? A0 : A1) : A0;
    const __half* Wz = Wt + (size_t)bz * bstride;
    TC* Cz = C + (size_t)bz * cstride;
    const float alpha = PROJ ? ((bz % 3 == 0) ? alpha0 : 1.0f) : alpha0;

    const int wm = (w & 3) * 32, wn = (w >> 2) * 64;
    const int lr = lane >> 2, lc = lane & 3;

    // per-lane LDSM base offsets (relative to stage base, bytes)
    const int lrow = lane & 15, lcol = (lane >> 4) * 16;
    const uint32_t aoff0 = (uint32_t)((wm + lrow) * ROWB + lcol);
    const uint32_t aoff1 = aoff0 + 16 * ROWB;
    uint32_t boff[4];
#pragma unroll
    for (int nb = 0; nb < 4; nb++)
        boff[nb] = (uint32_t)(A_BYTES + (wn + nb * 16 + lrow) * ROWB + lcol);

    float acc[2][8][4];
#pragma unroll
    for (int i = 0; i < 2; i++)
#pragma unroll
        for (int j = 0; j < 8; j++)
#pragma unroll
            for (int k = 0; k < 4; k++) acc[i][j][k] = 0.f;

    // cp.async coords: 8 chunks per row, 128 rows each for A and B
    auto load_stage = [&](int s, int k0) {
        const __half* Ab = Az;
        int kl = k0;
        if (SPLITA && k0 >= ksplit) { Ab = A1; kl = k0 - ksplit; }
        uint32_t abase = sb + (uint32_t)s * STG_BYTES;
        uint32_t bbase = abase + A_BYTES;
#pragma unroll
        for (int i = 0; i < 4; i++) {
            int id = tid + i * 256;
            int r = id >> 3, q = id & 7;
            cpa16(abase + (uint32_t)(r * ROWB + q * 16),
                  Ab + (size_t)(bm + r) * lda + kl + q * 8);
        }
#pragma unroll
        for (int i = 0; i < 4; i++) {
            int id = tid + i * 256;
            int r = id >> 3, q = id & 7;
            cpa16(bbase + (uint32_t)(r * ROWB + q * 16),
                  Wz + (size_t)(bn + r) * K + k0 + q * 8);
        }
    };

    const int nt = K >> 6;
    load_stage(0, 0);  cpa_commit();
    load_stage(1, 64); cpa_commit();

    for (int t = 0; t < nt; t++) {
        cpa_wait<1>();
        __syncthreads();
        if (t + 2 < nt) load_stage((t + 2) % NST, (t + 2) << 6);
        cpa_commit();

        const uint32_t stg = sb + (uint32_t)(t % NST) * STG_BYTES;
#pragma unroll
        for (int kk = 0; kk < 4; kk++) {      // 4 x k16 chunks (32B each)
            const uint32_t kb = kk * 32;
            uint32_t af[2][4];
            ldsm4(af[0], stg + aoff0 + kb);
            ldsm4(af[1], stg + aoff1 + kb);
            uint32_t bf[4][4];
#pragma unroll
            for (int nb = 0; nb < 4; nb++) ldsm4(bf[nb], stg + boff[nb] + kb);
#pragma unroll
            for (int mi = 0; mi < 2; mi++)
#pragma unroll
                for (int nb = 0; nb < 4; nb++) {
                    uint32_t b0[2] = { bf[nb][0], bf[nb][2] };
                    uint32_t b1[2] = { bf[nb][1], bf[nb][3] };
                    mma16(acc[mi][2 * nb],     af[mi], b0);
                    mma16(acc[mi][2 * nb + 1], af[mi], b1);
                }
        }
    }

    // epilogue (N fixed at 512)
#pragma unroll
    for (int mi = 0; mi < 2; mi++) {
#pragma unroll
        for (int ni = 0; ni < 8; ni++) {
            int row = bm + wm + mi * 16 + lr;
            int col = bn + wn + ni * 8 + lc * 2;
            float b0 = 0.f, b1 = 0.f;
            if (bias) { b0 = bias[col]; b1 = bias[col + 1]; }
            float v0 = acc[mi][ni][0] * alpha + b0;
            float v1 = acc[mi][ni][1] * alpha + b1;
            float v2 = acc[mi][ni][2] * alpha + b0;
            float v3 = acc[mi][ni][3] * alpha + b1;
            if (RELU) {
                v0 = fmaxf(v0, 0.f); v1 = fmaxf(v1, 0.f);
                v2 = fmaxf(v2, 0.f); v3 = fmaxf(v3, 0.f);
            }
            st2(Cz + (size_t)row * 512 + col, v0, v1);
            st2(Cz + (size_t)(row + 8) * 512 + col, v2, v3);
        }
    }
}

// ============================ Attention ===================================
// grid (2048, 2): y==0: a1 = softmax(q1 k2^T) v1 ; y==1: a2 = softmax(q2 k1^T) v2.
// O aliases V (per-column-chunk read-then-write, disjoint chunks).
// Phase 1: 3-stage cp.async Q/K pipeline, fragments via ldmatrix.
// Phase 3: reg-pipelined V LDG with 2-stage smem.
constexpr int QW = 36, SLD = 68, VW = 72;
constexpr int QST = 64 * QW;   // 2304 words / stage
constexpr size_t ATTN_SMEM = (size_t)6 * QST * 4;   // 55296 B

__global__ void __launch_bounds__(256, 2) attn_kernel(
    const __half* __restrict__ q1, const __half* __restrict__ k1, __half* __restrict__ v1,
    const __half* __restrict__ q2, const __half* __restrict__ k2, __half* __restrict__ v2)
{
    extern __shared__ uint32_t asmem[];
    uint32_t* sQ = asmem;            // 3 stages Q; later S (fp32)
    uint32_t* sK = asmem + 3 * QST;  // 3 stages K; later P (stage0) + V (1,2)

    const int tid = threadIdx.x, w = tid >> 5, lane = tid & 31;
    const int lr = lane >> 2, lc = lane & 3;
    const int wm = (w & 3) * 16;
    const int wn = (w >> 2) * 32;
    const size_t base = (size_t)blockIdx.x * (64 * 512);

    const __half *Q, *Kx;  __half* V;
    if (blockIdx.y == 0) { Q = q1; Kx = k2; V = v1; }
    else                 { Q = q2; Kx = k1; V = v2; }
    __half* O = V;

    const uint32_t qsm = (uint32_t)__cvta_generic_to_shared(sQ);
    const uint32_t ksm = (uint32_t)__cvta_generic_to_shared(sK);

    // LDSM per-lane offsets (bytes, relative to stage base; row = 144 B)
    const int lrow = lane & 15, lcol = (lane >> 4) * 16;
    const uint32_t qoff = (uint32_t)((wm + lrow) * 144 + lcol);
    const uint32_t koff0 = (uint32_t)((wn + lrow) * 144 + lcol);
    const uint32_t koff1 = koff0 + 16 * 144;

    auto loadQK = [&](int st, int hc) {
#pragma unroll
        for (int i = 0; i < 2; i++) {
            int id = tid + i * 256;
            int r = id >> 3, q = id & 7;
            uint32_t off = (uint32_t)(st * QST + r * QW + q * 4) * 4;
            cpa16(qsm + off, Q  + base + (size_t)r * 512 + hc + q * 8);
            cpa16(ksm + off, Kx + base + (size_t)r * 512 + hc + q * 8);
        }
    };

    float sacc[4][4];
#pragma unroll
    for (int i = 0; i < 4; i++)
#pragma unroll
        for (int j = 0; j < 4; j++) sacc[i][j] = 0.f;

    loadQK(0, 0);   cpa_commit();
    loadQK(1, 64);  cpa_commit();
    for (int c = 0; c < 8; c++) {
        cpa_wait<1>();
        __syncthreads();
        if (c + 2 < 8) loadQK((c + 2) % 3, (c + 2) * 64);
        cpa_commit();

        const uint32_t qstg = qsm + (uint32_t)((c % 3) * QST) * 4;
        const uint32_t kstg = ksm + (uint32_t)((c % 3) * QST) * 4;
#pragma unroll
        for (int kk = 0; kk < 4; kk++) {
            const uint32_t kb = kk * 32;
            uint32_t af[4], kf0[4], kf1[4];
            ldsm4(af,  qstg + qoff  + kb);
            ldsm4(kf0, kstg + koff0 + kb);
            ldsm4(kf1, kstg + koff1 + kb);
            uint32_t b00[2] = { kf0[0], kf0[2] }, b01[2] = { kf0[1], kf0[3] };
            uint32_t b10[2] = { kf1[0], kf1[2] }, b11[2] = { kf1[1], kf1[3] };
            mma16(sacc[0], af, b00);
            mma16(sacc[1], af, b01);
            mma16(sacc[2], af, b10);
            mma16(sacc[3], af, b11);
        }
    }
    __syncthreads();

    float* S = reinterpret_cast<float*>(sQ);
#pragma unroll
    for (int ni = 0; ni < 4; ni++) {
        int row = wm + lr, col = wn + ni * 8 + lc * 2;
        S[row * SLD + col]           = sacc[ni][0];
        S[row * SLD + col + 1]       = sacc[ni][1];
        S[(row + 8) * SLD + col]     = sacc[ni][2];
        S[(row + 8) * SLD + col + 1] = sacc[ni][3];
    }
    __syncthreads();

    for (int r = w * 8; r < w * 8 + 8; r++) {
        float v0 = S[r * SLD + lane], v1 = S[r * SLD + 32 + lane];
        float m = fmaxf(v0, v1);
#pragma unroll
        for (int o = 16; o > 0; o >>= 1) m = fmaxf(m, __shfl_xor_sync(0xffffffffu, m, o));
        float e0 = __expf(v0 - m), e1 = __expf(v1 - m);
        float s = e0 + e1;
#pragma unroll
        for (int o = 16; o > 0; o >>= 1) s += __shfl_xor_sync(0xffffffffu, s, o);
        float inv = 1.f / s;
        S[r * SLD + lane]      = e0 * inv;
        S[r * SLD + 32 + lane] = e1 * inv;
    }
    __syncthreads();

    uint32_t* Pw = sK;
    for (int idx = tid; idx < 64 * 32; idx += 256) {
        int row = idx >> 5, mp = idx & 31;
        Pw[row * QW + mp] = pk(S[row * SLD + 2 * mp], S[row * SLD + 2 * mp + 1]);
    }
    __syncthreads();

    uint32_t paf[4][4];
#pragma unroll
    for (int c = 0; c < 4; c++) {
        int kk2 = c * 8, r0 = wm + lr;
        paf[c][0] = Pw[r0 * QW + kk2 + lc];
        paf[c][1] = Pw[(r0 + 8) * QW + kk2 + lc];
        paf[c][2] = Pw[r0 * QW + kk2 + lc + 4];
        paf[c][3] = Pw[(r0 + 8) * QW + kk2 + lc + 4];
    }
    __syncthreads();

    const int mp0 = tid >> 4, h40 = (tid & 15) * 4;
    const int mp1 = (tid + 256) >> 4, h41 = ((tid + 256) & 15) * 4;

    uint2 ra0, rb0, ra1, rb1;
    auto ldV = [&](int hc) {
        ra0 = *reinterpret_cast<const uint2*>(V + base + (size_t)(2 * mp0) * 512 + hc + h40);
        rb0 = *reinterpret_cast<const uint2*>(V + base + (size_t)(2 * mp0 + 1) * 512 + hc + h40);
        ra1 = *reinterpret_cast<const uint2*>(V + base + (size_t)(2 * mp1) * 512 + hc + h41);
        rb1 = *reinterpret_cast<const uint2*>(V + base + (size_t)(2 * mp1 + 1) * 512 + hc + h41);
    };
    ldV(0);

    for (int ci = 0; ci < 8; ci++) {
        int hc = ci * 64;
        uint32_t* vb = sK + (1 + (ci & 1)) * QST;
        *reinterpret_cast<uint4*>(&vb[mp0 * VW + h40]) =
            make_uint4(__byte_perm(ra0.x, rb0.x, 0x5410), __byte_perm(ra0.x, rb0.x, 0x7632),
                       __byte_perm(ra0.y, rb0.y, 0x5410), __byte_perm(ra0.y, rb0.y, 0x7632));
        *reinterpret_cast<uint4*>(&vb[mp1 * VW + h41]) =
            make_uint4(__byte_perm(ra1.x, rb1.x, 0x5410), __byte_perm(ra1.x, rb1.x, 0x7632),
                       __byte_perm(ra1.y, rb1.y, 0x5410), __byte_perm(ra1.y, rb1.y, 0x7632));
        __syncthreads();

        if (ci + 1 < 8) ldV(hc + 64);

        float oacc[4][4];
#pragma unroll
        for (int i = 0; i < 4; i++)
#pragma unroll
            for (int j = 0; j < 4; j++) oacc[i][j] = 0.f;
#pragma unroll
        for (int c = 0; c < 4; c++) {
            int kk2 = c * 8;
#pragma unroll
            for (int ni = 0; ni < 4; ni++) {
                int c0 = wn + ni * 8 + lr;
                uint32_t bf[2] = { vb[(kk2 + lc) * VW + c0],
                                   vb[(kk2 + lc + 4) * VW + c0] };
                mma16(oacc[ni], paf[c], bf);
            }
        }
#pragma unroll
        for (int ni = 0; ni < 4; ni++) {
            int row = wm + lr, col = wn + ni * 8 + lc * 2;
            st2(O + base + (size_t)row * 512 + hc + col,       oacc[ni][0], oacc[ni][1]);
            st2(O + base + (size_t)(row + 8) * 512 + hc + col, oacc[ni][2], oacc[ni][3]);
        }
    }
}

// ============================== launch ====================================
extern "C" void kernel_launch(void* const* d_in, const int* in_sizes, int n_in,
                              void* d_out, int out_size)
{
    const float* x1  = (const float*)d_in[0];
    const float* x2  = (const float*)d_in[1];
    const float* b1  = (const float*)d_in[9];
    const float* b2  = (const float*)d_in[11];
    float* out = (float*)d_out;

    __half* s;  __half* wbase;
    cudaGetSymbolAddress((void**)&s, g_h);
    cudaGetSymbolAddress((void**)&wbase, g_w);

    __half* q1 = s + 0 * BUF;
    __half* k1 = s + 1 * BUF;
    __half* v1 = s + 2 * BUF;
    __half* q2 = s + 3 * BUF;
    __half* k2 = s + 4 * BUF;
    __half* v2 = s + 5 * BUF;
    __half* xh1 = s + 6 * BUF;
    __half* xh2 = xh1 + XBUF;
    __half* a1 = v1;   // attention output aliases V
    __half* a2 = v2;
    __half* h  = q1;   // MLP hidden reuses q1

    __half* wqkvT = wbase;                    // 6 x (512*256), z-major
    __half* w1T   = wbase + 6 * 131072;       // 512*1024
    __half* w2T   = w1T + 512 * 1024;         // 512*512

    const float scale = 0.0625f;  // 256^-0.5
    dim3 blk(256);

    cudaFuncSetAttribute(gemm_l<__half, false, false, true >, cudaFuncAttributeMaxDynamicSharedMemorySize, (int)GEMM_SMEM);
    cudaFuncSetAttribute(gemm_l<__half, true,  true,  false>, cudaFuncAttributeMaxDynamicSharedMemorySize, (int)GEMM_SMEM);
    cudaFuncSetAttribute(gemm_l<float,  false, false, false>, cudaFuncAttributeMaxDynamicSharedMemorySize, (int)GEMM_SMEM);
    cudaFuncSetAttribute(attn_kernel, cudaFuncAttributeMaxDynamicSharedMemorySize, (int)ATTN_SMEM);

    // ---- pre-pass: fp16 x copies + transposed fp16 weights ----
    cvt_f2h<<<4096, 256>>>(x1, xh1, (int)(XBUF / 4));
    cvt_f2h<<<4096, 256>>>(x2, xh2, (int)(XBUF / 4));
    WSrc ws;
    ws.w[0] = (const float*)d_in[2];  // Wq1
    ws.w[1] = (const float*)d_in[3];  // Wk1
    ws.w[2] = (const float*)d_in[4];  // Wv1
    ws.w[3] = (const float*)d_in[5];  // Wq2
    ws.w[4] = (const float*)d_in[6];  // Wk2
    ws.w[5] = (const float*)d_in[7];  // Wv2
    ws.w[6] = (const float*)d_in[8];  // W1
    ws.w[7] = (const float*)d_in[10]; // W2
    pack_wT<<<2048, 256>>>(ws, wbase);

    // ---- stage 1: all 6 projections in ONE launch (z: 0..5) ----
    dim3 gproj(4, MROWS / 128, 6);
    gemm_l<__half, false, false, true><<<gproj, blk, GEMM_SMEM>>>(
        xh1, xh2, wqkvT, nullptr, q1, D_, 0, D_, 131072, BUF, scale);

    // ---- stage 2: both cross attentions in ONE launch ----
    attn_kernel<<<dim3(BT, 2), blk, ATTN_SMEM>>>(q1, k1, v1, q2, k2, v2);

    // ---- stage 3: MLP ----
    dim3 gmlp(4, MROWS / 128, 1);
    gemm_l<__half, true, true, false><<<gmlp, blk, GEMM_SMEM>>>(
        a1, a2, w1T, b1, h, 2 * H_, H_, H_, 0, 0, 1.f);
    gemm_l<float, false, false, false><<<gmlp, blk, GEMM_SMEM>>>(
        h, nullptr, w2T, b2, out, H_, 0, H_, 0, 0, 1.f);
}

// round 11
// speedup vs baseline: 1.0003x; 1.0003x over previous
#include <cuda_runtime.h>
#include <cuda_fp16.h>
#include <cstdint>

// Problem constants
constexpr int B_ = 16, T_ = 128, N_ = 64, D_ = 256, H_ = 512;
constexpr int MROWS = B_ * T_ * N_;          // 131072 flattened rows
constexpr int BT   = B_ * T_;                // 2048 attention problems
constexpr size_t BUF  = (size_t)MROWS * H_;  // 67.1M elems (q/k/v buffers)
constexpr size_t XBUF = (size_t)MROWS * D_;  // fp16 copies of x

// ---------------- scratch (device globals) ---------------------------------
__device__ __align__(16) __half g_h[6 * BUF + 2 * XBUF];
// transposed fp16 weights [N=512, K] row-major:
// 6 x (512*256) + (512*1024) + (512*512) = 1,572,864 halves (3 MB)
__device__ __align__(16) __half g_w[1572864];

__device__ __forceinline__ uint32_t pk(float a, float b) {
    __half2 h = __floats2half2_rn(a, b);
    return *reinterpret_cast<uint32_t*>(&h);
}
__device__ __forceinline__ void st2(float* p, float v0, float v1) {
    *reinterpret_cast<float2*>(p) = make_float2(v0, v1);
}
__device__ __forceinline__ void st2(__half* p, float v0, float v1) {
    *reinterpret_cast<__half2*>(p) = __floats2half2_rn(v0, v1);
}

// mma.sync m16n8k16, all operands BY VALUE so ptxas binds LDSM outputs
// directly into HMMA operands (no register-array marshalling MOVs).
__device__ __forceinline__ void mma16v(float* d,
    uint32_t a0, uint32_t a1, uint32_t a2, uint32_t a3,
    uint32_t b0, uint32_t b1) {
    asm volatile(
        "mma.sync.aligned.m16n8k16.row.col.f32.f16.f16.f32 "
        "{%0,%1,%2,%3}, {%4,%5,%6,%7}, {%8,%9}, {%0,%1,%2,%3};"
        : "+f"(d[0]), "+f"(d[1]), "+f"(d[2]), "+f"(d[3])
        : "r"(a0), "r"(a1), "r"(a2), "r"(a3), "r"(b0), "r"(b1));
}

// ldmatrix x4: four 8x8 b16 tiles; result lane layout == mma fragment layout.
__device__ __forceinline__ void ldsm4(uint32_t* r, uint32_t addr) {
    asm volatile("ldmatrix.sync.aligned.m8n8.x4.shared.b16 {%0,%1,%2,%3}, [%4];"
        : "=r"(r[0]), "=r"(r[1]), "=r"(r[2]), "=r"(r[3]) : "r"(addr));
}

__device__ __forceinline__ void cpa16(uint32_t dst_smem, const void* src) {
    asm volatile("cp.async.cg.shared.global [%0], [%1], 16;" :: "r"(dst_smem), "l"(src));
}
__device__ __forceinline__ void cpa_commit() { asm volatile("cp.async.commit_group;"); }
template<int Ngrp> __device__ __forceinline__ void cpa_wait() {
    asm volatile("cp.async.wait_group %0;" :: "n"(Ngrp));
}

// ======================= conversion pre-pass ==============================
__global__ void cvt_f2h(const float* __restrict__ src, __half* __restrict__ dst, int n4) {
    for (int i = blockIdx.x * blockDim.x + threadIdx.x; i < n4; i += gridDim.x * blockDim.x) {
        float4 v = reinterpret_cast<const float4*>(src)[i];
        reinterpret_cast<uint2*>(dst)[i] = make_uint2(pk(v.x, v.y), pk(v.z, v.w));
    }
}
// Transpose-pack all weights: W[K,512] fp32 -> Wt[512,K] fp16 regions.
struct WSrc { const float* w[8]; };
__global__ void pack_wT(WSrc ws, __half* __restrict__ out) {
    constexpr int R6 = 6 * 131072;            // 786432 (6 x 512*256)
    constexpr int R7 = R6 + 512 * 1024;       // 1310720
    constexpr int TOT = R7 + 512 * 512;       // 1572864
    for (int i = blockIdx.x * blockDim.x + threadIdx.x; i < TOT; i += gridDim.x * blockDim.x) {
        const float* W; int local, K;
        if (i < R6)      { W = ws.w[i / 131072]; local = i % 131072; K = 256; }
        else if (i < R7) { W = ws.w[6];          local = i - R6;     K = 1024; }
        else             { W = ws.w[7];          local = i - R7;     K = 512; }
        int n = local / K, k = local % K;
        out[i] = __float2half_rn(W[(size_t)k * 512 + n]);
    }
}

// =============================== GEMM =====================================
// C[M,512] = act( alpha * (A @ Wt^T) + bias ).  A fp16 [M,K] row-major,
// Wt fp16 [512,K] row-major. Both smem tiles K-major, rows padded to 144 B
// (rows land on distinct 16B groups mod 128 -> LDSM conflict-free).
// 128x128x64 tiles, 3-slot / 2-ahead cp.async pipeline, 256 thr, 8 warps
// (4m x 2n), fragments via ldmatrix.x4, by-value mma operands.
constexpr int ROWB = 144;                 // bytes per smem row (36 words)
constexpr int A_BYTES = 128 * ROWB;       // 18432
constexpr int STG_BYTES = 2 * A_BYTES;    // 36864 (A then B)
constexpr int NST = 3;
constexpr size_t GEMM_SMEM = (size_t)STG_BYTES * NST;   // 110592 B

template<typename TC, bool RELU, bool SPLITA, bool PROJ>
__global__ void __launch_bounds__(256, 2) gemm_l(
    const __half* __restrict__ A0, const __half* __restrict__ A1,
    const __half* __restrict__ Wt, const float* __restrict__ bias,
    TC* __restrict__ C, int K, int ksplit, int lda,
    size_t bstride, size_t cstride, float alpha0)
{
    extern __shared__ __align__(1024) uint8_t smem[];
    const uint32_t sb = (uint32_t)__cvta_generic_to_shared(smem);

    const int tid = threadIdx.x, w = tid >> 5, lane = tid & 31;
    const int bm = blockIdx.y * 128;
    const int bn = blockIdx.x * 128;
    const int bz = blockIdx.z;
    const __half* Az = PROJ ? (bz < 3 ? A0 : A1) : A0;
    const __half* Wz = Wt + (size_t)bz * bstride;
    TC* Cz = C + (size_t)bz * cstride;
    const float alpha = PROJ ? ((bz % 3 == 0) ? alpha0 : 1.0f) : alpha0;

    const int wm = (w & 3) * 32, wn = (w >> 2) * 64;
    const int lr = lane >> 2, lc = lane & 3;

    // per-lane LDSM base offsets (relative to stage base, bytes)
    const int lrow = lane & 15, lcol = (lane >> 4) * 16;
    const uint32_t aoff0 = (uint32_t)((wm + lrow) * ROWB + lcol);
    const uint32_t aoff1 = aoff0 + 16 * ROWB;
    const uint32_t boff0 = (uint32_t)(A_BYTES + (wn + lrow) * ROWB + lcol);

    float acc[2][8][4];
#pragma unroll
    for (int i = 0; i < 2; i++)
#pragma unroll
        for (int j = 0; j < 8; j++)
#pragma unroll
            for (int k = 0; k < 4; k++) acc[i][j][k] = 0.f;

    auto load_stage = [&](int s, int k0) {
        const __half* Ab = Az;
        int kl = k0;
        if (SPLITA && k0 >= ksplit) { Ab = A1; kl = k0 - ksplit; }
        uint32_t abase = sb + (uint32_t)s * STG_BYTES;
        uint32_t bbase = abase + A_BYTES;
#pragma unroll
        for (int i = 0; i < 4; i++) {
            int id = tid + i * 256;
            int r = id >> 3, q = id & 7;
            cpa16(abase + (uint32_t)(r * ROWB + q * 16),
                  Ab + (size_t)(bm + r) * lda + kl + q * 8);
        }
#pragma unroll
        for (int i = 0; i < 4; i++) {
            int id = tid + i * 256;
            int r = id >> 3, q = id & 7;
            cpa16(bbase + (uint32_t)(r * ROWB + q * 16),
                  Wz + (size_t)(bn + r) * K + k0 + q * 8);
        }
    };

    const int nt = K >> 6;
    load_stage(0, 0);  cpa_commit();
    load_stage(1, 64); cpa_commit();

    for (int t = 0; t < nt; t++) {
        cpa_wait<1>();
        __syncthreads();
        if (t + 2 < nt) load_stage((t + 2) % NST, (t + 2) << 6);
        cpa_commit();

        const uint32_t stg = sb + (uint32_t)(t % NST) * STG_BYTES;
#pragma unroll
        for (int kk = 0; kk < 4; kk++) {      // 4 x k16 chunks (32B each)
            const uint32_t kb = kk * 32;
            uint32_t af[2][4];
            ldsm4(af[0], stg + aoff0 + kb);
            ldsm4(af[1], stg + aoff1 + kb);
            uint32_t bf[4][4];
#pragma unroll
            for (int nb = 0; nb < 4; nb++)
                ldsm4(bf[nb], stg + boff0 + (uint32_t)(nb * 16 * ROWB) + kb);
#pragma unroll
            for (int mi = 0; mi < 2; mi++)
#pragma unroll
                for (int nb = 0; nb < 4; nb++) {
                    mma16v(acc[mi][2 * nb],
                           af[mi][0], af[mi][1], af[mi][2], af[mi][3],
                           bf[nb][0], bf[nb][2]);
                    mma16v(acc[mi][2 * nb + 1],
                           af[mi][0], af[mi][1], af[mi][2], af[mi][3],
                           bf[nb][1], bf[nb][3]);
                }
        }
    }

    // epilogue (N fixed at 512)
#pragma unroll
    for (int mi = 0; mi < 2; mi++) {
#pragma unroll
        for (int ni = 0; ni < 8; ni++) {
            int row = bm + wm + mi * 16 + lr;
            int col = bn + wn + ni * 8 + lc * 2;
            float b0 = 0.f, b1 = 0.f;
            if (bias) { b0 = bias[col]; b1 = bias[col + 1]; }
            float v0 = acc[mi][ni][0] * alpha + b0;
            float v1 = acc[mi][ni][1] * alpha + b1;
            float v2 = acc[mi][ni][2] * alpha + b0;
            float v3 = acc[mi][ni][3] * alpha + b1;
            if (RELU) {
                v0 = fmaxf(v0, 0.f); v1 = fmaxf(v1, 0.f);
                v2 = fmaxf(v2, 0.f); v3 = fmaxf(v3, 0.f);
            }
            st2(Cz + (size_t)row * 512 + col, v0, v1);
            st2(Cz + (size_t)(row + 8) * 512 + col, v2, v3);
        }
    }
}

// ============================ Attention ===================================
// grid (2048, 2): y==0: a1 = softmax(q1 k2^T) v1 ; y==1: a2 = softmax(q2 k1^T) v2.
// O aliases V (per-column-chunk read-then-write, disjoint chunks).
// Phase 1: 3-stage cp.async Q/K pipeline, fragments via ldmatrix (by-value mma).
// Phase 3: reg-pipelined V LDG with 2-stage smem.
constexpr int QW = 36, SLD = 68, VW = 72;
constexpr int QST = 64 * QW;   // 2304 words / stage
constexpr size_t ATTN_SMEM = (size_t)6 * QST * 4;   // 55296 B

__global__ void __launch_bounds__(256, 2) attn_kernel(
    const __half* __restrict__ q1, const __half* __restrict__ k1, __half* __restrict__ v1,
    const __half* __restrict__ q2, const __half* __restrict__ k2, __half* __restrict__ v2)
{
    extern __shared__ uint32_t asmem[];
    uint32_t* sQ = asmem;            // 3 stages Q; later S (fp32)
    uint32_t* sK = asmem + 3 * QST;  // 3 stages K; later P (stage0) + V (1,2)

    const int tid = threadIdx.x, w = tid >> 5, lane = tid & 31;
    const int lr = lane >> 2, lc = lane & 3;
    const int wm = (w & 3) * 16;
    const int wn = (w >> 2) * 32;
    const size_t base = (size_t)blockIdx.x * (64 * 512);

    const __half *Q, *Kx;  __half* V;
    if (blockIdx.y == 0) { Q = q1; Kx = k2; V = v1; }
    else                 { Q = q2; Kx = k1; V = v2; }
    __half* O = V;

    const uint32_t qsm = (uint32_t)__cvta_generic_to_shared(sQ);
    const uint32_t ksm = (uint32_t)__cvta_generic_to_shared(sK);

    // LDSM per-lane offsets (bytes, relative to stage base; row = 144 B)
    const int lrow = lane & 15, lcol = (lane >> 4) * 16;
    const uint32_t qoff = (uint32_t)((wm + lrow) * 144 + lcol);
    const uint32_t koff0 = (uint32_t)((wn + lrow) * 144 + lcol);
    const uint32_t koff1 = koff0 + 16 * 144;

    auto loadQK = [&](int st, int hc) {
#pragma unroll
        for (int i = 0; i < 2; i++) {
            int id = tid + i * 256;
            int r = id >> 3, q = id & 7;
            uint32_t off = (uint32_t)(st * QST + r * QW + q * 4) * 4;
            cpa16(qsm + off, Q  + base + (size_t)r * 512 + hc + q * 8);
            cpa16(ksm + off, Kx + base + (size_t)r * 512 + hc + q * 8);
        }
    };

    float sacc[4][4];
#pragma unroll
    for (int i = 0; i < 4; i++)
#pragma unroll
        for (int j = 0; j < 4; j++) sacc[i][j] = 0.f;

    loadQK(0, 0);   cpa_commit();
    loadQK(1, 64);  cpa_commit();
    for (int c = 0; c < 8; c++) {
        cpa_wait<1>();
        __syncthreads();
        if (c + 2 < 8) loadQK((c + 2) % 3, (c + 2) * 64);
        cpa_commit();

        const uint32_t qstg = qsm + (uint32_t)((c % 3) * QST) * 4;
        const uint32_t kstg = ksm + (uint32_t)((c % 3) * QST) * 4;
#pragma unroll
        for (int kk = 0; kk < 4; kk++) {
            const uint32_t kb = kk * 32;
            uint32_t af[4], kf0[4], kf1[4];
            ldsm4(af,  qstg + qoff  + kb);
            ldsm4(kf0, kstg + koff0 + kb);
            ldsm4(kf1, kstg + koff1 + kb);
            mma16v(sacc[0], af[0], af[1], af[2], af[3], kf0[0], kf0[2]);
            mma16v(sacc[1], af[0], af[1], af[2], af[3], kf0[1], kf0[3]);
            mma16v(sacc[2], af[0], af[1], af[2], af[3], kf1[0], kf1[2]);
            mma16v(sacc[3], af[0], af[1], af[2], af[3], kf1[1], kf1[3]);
        }
    }
    __syncthreads();

    float* S = reinterpret_cast<float*>(sQ);
#pragma unroll
    for (int ni = 0; ni < 4; ni++) {
        int row = wm + lr, col = wn + ni * 8 + lc * 2;
        S[row * SLD + col]           = sacc[ni][0];
        S[row * SLD + col + 1]       = sacc[ni][1];
        S[(row + 8) * SLD + col]     = sacc[ni][2];
        S[(row + 8) * SLD + col + 1] = sacc[ni][3];
    }
    __syncthreads();

    for (int r = w * 8; r < w * 8 + 8; r++) {
        float v0 = S[r * SLD + lane], v1 = S[r * SLD + 32 + lane];
        float m = fmaxf(v0, v1);
#pragma unroll
        for (int o = 16; o > 0; o >>= 1) m = fmaxf(m, __shfl_xor_sync(0xffffffffu, m, o));
        float e0 = __expf(v0 - m), e1 = __expf(v1 - m);
        float s = e0 + e1;
#pragma unroll
        for (int o = 16; o > 0; o >>= 1) s += __shfl_xor_sync(0xffffffffu, s, o);
        float inv = 1.f / s;
        S[r * SLD + lane]      = e0 * inv;
        S[r * SLD + 32 + lane] = e1 * inv;
    }
    __syncthreads();

    uint32_t* Pw = sK;
    for (int idx = tid; idx < 64 * 32; idx += 256) {
        int row = idx >> 5, mp = idx & 31;
        Pw[row * QW + mp] = pk(S[row * SLD + 2 * mp], S[row * SLD + 2 * mp + 1]);
    }
    __syncthreads();

    uint32_t paf[4][4];
#pragma unroll
    for (int c = 0; c < 4; c++) {
        int kk2 = c * 8, r0 = wm + lr;
        paf[c][0] = Pw[r0 * QW + kk2 + lc];
        paf[c][1] = Pw[(r0 + 8) * QW + kk2 + lc];
        paf[c][2] = Pw[r0 * QW + kk2 + lc + 4];
        paf[c][3] = Pw[(r0 + 8) * QW + kk2 + lc + 4];
    }
    __syncthreads();

    const int mp0 = tid >> 4, h40 = (tid & 15) * 4;
    const int mp1 = (tid + 256) >> 4, h41 = ((tid + 256) & 15) * 4;

    uint2 ra0, rb0, ra1, rb1;
    auto ldV = [&](int hc) {
        ra0 = *reinterpret_cast<const uint2*>(V + base + (size_t)(2 * mp0) * 512 + hc + h40);
        rb0 = *reinterpret_cast<const uint2*>(V + base + (size_t)(2 * mp0 + 1) * 512 + hc + h40);
        ra1 = *reinterpret_cast<const uint2*>(V + base + (size_t)(2 * mp1) * 512 + hc + h41);
        rb1 = *reinterpret_cast<const uint2*>(V + base + (size_t)(2 * mp1 + 1) * 512 + hc + h41);
    };
    ldV(0);

    for (int ci = 0; ci < 8; ci++) {
        int hc = ci * 64;
        uint32_t* vb = sK + (1 + (ci & 1)) * QST;
        *reinterpret_cast<uint4*>(&vb[mp0 * VW + h40]) =
            make_uint4(__byte_perm(ra0.x, rb0.x, 0x5410), __byte_perm(ra0.x, rb0.x, 0x7632),
                       __byte_perm(ra0.y, rb0.y, 0x5410), __byte_perm(ra0.y, rb0.y, 0x7632));
        *reinterpret_cast<uint4*>(&vb[mp1 * VW + h41]) =
            make_uint4(__byte_perm(ra1.x, rb1.x, 0x5410), __byte_perm(ra1.x, rb1.x, 0x7632),
                       __byte_perm(ra1.y, rb1.y, 0x5410), __byte_perm(ra1.y, rb1.y, 0x7632));
        __syncthreads();

        if (ci + 1 < 8) ldV(hc + 64);

        float oacc[4][4];
#pragma unroll
        for (int i = 0; i < 4; i++)
#pragma unroll
            for (int j = 0; j < 4; j++) oacc[i][j] = 0.f;
#pragma unroll
        for (int c = 0; c < 4; c++) {
            int kk2 = c * 8;
#pragma unroll
            for (int ni = 0; ni < 4; ni++) {
                int c0 = wn + ni * 8 + lr;
                mma16v(oacc[ni], paf[c][0], paf[c][1], paf[c][2], paf[c][3],
                       vb[(kk2 + lc) * VW + c0], vb[(kk2 + lc + 4) * VW + c0]);
            }
        }
#pragma unroll
        for (int ni = 0; ni < 4; ni++) {
            int row = wm + lr, col = wn + ni * 8 + lc * 2;
            st2(O + base + (size_t)row * 512 + hc + col,       oacc[ni][0], oacc[ni][1]);
            st2(O + base + (size_t)(row + 8) * 512 + hc + col, oacc[ni][2], oacc[ni][3]);
        }
    }
}

// ============================== launch ====================================
extern "C" void kernel_launch(void* const* d_in, const int* in_sizes, int n_in,
                              void* d_out, int out_size)
{
    const float* x1  = (const float*)d_in[0];
    const float* x2  = (const float*)d_in[1];
    const float* b1  = (const float*)d_in[9];
    const float* b2  = (const float*)d_in[11];
    float* out = (float*)d_out;

    __half* s;  __half* wbase;
    cudaGetSymbolAddress((void**)&s, g_h);
    cudaGetSymbolAddress((void**)&wbase, g_w);

    __half* q1 = s + 0 * BUF;
    __half* k1 = s + 1 * BUF;
    __half* v1 = s + 2 * BUF;
    __half* q2 = s + 3 * BUF;
    __half* k2 = s + 4 * BUF;
    __half* v2 = s + 5 * BUF;
    __half* xh1 = s + 6 * BUF;
    __half* xh2 = xh1 + XBUF;
    __half* a1 = v1;   // attention output aliases V
    __half* a2 = v2;
    __half* h  = q1;   // MLP hidden reuses q1

    __half* wqkvT = wbase;                    // 6 x (512*256), z-major
    __half* w1T   = wbase + 6 * 131072;       // 512*1024
    __half* w2T   = w1T + 512 * 1024;         // 512*512

    const float scale = 0.0625f;  // 256^-0.5
    dim3 blk(256);

    cudaFuncSetAttribute(gemm_l<__half, false, false, true >, cudaFuncAttributeMaxDynamicSharedMemorySize, (int)GEMM_SMEM);
    cudaFuncSetAttribute(gemm_l<__half, true,  true,  false>, cudaFuncAttributeMaxDynamicSharedMemorySize, (int)GEMM_SMEM);
    cudaFuncSetAttribute(gemm_l<float,  false, false, false>, cudaFuncAttributeMaxDynamicSharedMemorySize, (int)GEMM_SMEM);
    cudaFuncSetAttribute(attn_kernel, cudaFuncAttributeMaxDynamicSharedMemorySize, (int)ATTN_SMEM);

    // ---- pre-pass: fp16 x copies + transposed fp16 weights ----
    cvt_f2h<<<4096, 256>>>(x1, xh1, (int)(XBUF / 4));
    cvt_f2h<<<4096, 256>>>(x2, xh2, (int)(XBUF / 4));
    WSrc ws;
    ws.w[0] = (const float*)d_in[2];  // Wq1
    ws.w[1] = (const float*)d_in[3];  // Wk1
    ws.w[2] = (const float*)d_in[4];  // Wv1
    ws.w[3] = (const float*)d_in[5];  // Wq2
    ws.w[4] = (const float*)d_in[6];  // Wk2
    ws.w[5] = (const float*)d_in[7];  // Wv2
    ws.w[6] = (const float*)d_in[8];  // W1
    ws.w[7] = (const float*)d_in[10]; // W2
    pack_wT<<<2048, 256>>>(ws, wbase);

    // ---- stage 1: all 6 projections in ONE launch (z: 0..5) ----
    dim3 gproj(4, MROWS / 128, 6);
    gemm_l<__half, false, false, true><<<gproj, blk, GEMM_SMEM>>>(
        xh1, xh2, wqkvT, nullptr, q1, D_, 0, D_, 131072, BUF, scale);

    // ---- stage 2: both cross attentions in ONE launch ----
    attn_kernel<<<dim3(BT, 2), blk, ATTN_SMEM>>>(q1, k1, v1, q2, k2, v2);

    // ---- stage 3: MLP ----
    dim3 gmlp(4, MROWS / 128, 1);
    gemm_l<__half, true, true, false><<<gmlp, blk, GEMM_SMEM>>>(
        a1, a2, w1T, b1, h, 2 * H_, H_, H_, 0, 0, 1.f);
    gemm_l<float, false, false, false><<<gmlp, blk, GEMM_SMEM>>>(
        h, nullptr, w2T, b2, out, H_, 0, H_, 0, 0, 1.f);
}

// round 12
// speedup vs baseline: 1.0126x; 1.0122x over previous
#include <cuda_runtime.h>
#include <cuda_fp16.h>
#include <cstdint>

// Problem constants
constexpr int B_ = 16, T_ = 128, N_ = 64, D_ = 256, H_ = 512;
constexpr int MROWS = B_ * T_ * N_;          // 131072 flattened rows
constexpr int BT   = B_ * T_;                // 2048 attention problems
constexpr size_t BUF  = (size_t)MROWS * H_;  // 67.1M elems (q/k/v buffers)
constexpr size_t XBUF = (size_t)MROWS * D_;  // fp16 copies of x

// ---------------- scratch (device globals) ---------------------------------
__device__ __align__(16) __half g_h[6 * BUF + 2 * XBUF];
// transposed fp16 weights [N=512, K] row-major:
// 6 x (512*256) + (512*1024) + (512*512) = 1,572,864 halves (3 MB)
__device__ __align__(16) __half g_w[1572864];

__device__ __forceinline__ uint32_t pk(float a, float b) {
    __half2 h = __floats2half2_rn(a, b);
    return *reinterpret_cast<uint32_t*>(&h);
}
__device__ __forceinline__ void st2(float* p, float v0, float v1) {
    *reinterpret_cast<float2*>(p) = make_float2(v0, v1);
}
__device__ __forceinline__ void st2(__half* p, float v0, float v1) {
    *reinterpret_cast<__half2*>(p) = __floats2half2_rn(v0, v1);
}

// mma.sync m16n8k16 fp16 in / fp32 accum
__device__ __forceinline__ void mma16v(float* d,
    uint32_t a0, uint32_t a1, uint32_t a2, uint32_t a3,
    uint32_t b0, uint32_t b1) {
    asm volatile(
        "mma.sync.aligned.m16n8k16.row.col.f32.f16.f16.f32 "
        "{%0,%1,%2,%3}, {%4,%5,%6,%7}, {%8,%9}, {%0,%1,%2,%3};"
        : "+f"(d[0]), "+f"(d[1]), "+f"(d[2]), "+f"(d[3])
        : "r"(a0), "r"(a1), "r"(a2), "r"(a3), "r"(b0), "r"(b1));
}

// ldmatrix x4: four 8x8 b16 tiles; result lane layout == mma fragment layout.
__device__ __forceinline__ void ldsm4(uint32_t* r, uint32_t addr) {
    asm volatile("ldmatrix.sync.aligned.m8n8.x4.shared.b16 {%0,%1,%2,%3}, [%4];"
        : "=r"(r[0]), "=r"(r[1]), "=r"(r[2]), "=r"(r[3]) : "r"(addr));
}

__device__ __forceinline__ void cpa16(uint32_t dst_smem, const void* src) {
    asm volatile("cp.async.cg.shared.global [%0], [%1], 16;" :: "r"(dst_smem), "l"(src));
}
__device__ __forceinline__ void cpa_commit() { asm volatile("cp.async.commit_group;"); }
template<int Ngrp> __device__ __forceinline__ void cpa_wait() {
    asm volatile("cp.async.wait_group %0;" :: "n"(Ngrp));
}

// ======================= conversion pre-pass ==============================
__global__ void cvt_f2h(const float* __restrict__ src, __half* __restrict__ dst, int n4) {
    for (int i = blockIdx.x * blockDim.x + threadIdx.x; i < n4; i += gridDim.x * blockDim.x) {
        float4 v = reinterpret_cast<const float4*>(src)[i];
        reinterpret_cast<uint2*>(dst)[i] = make_uint2(pk(v.x, v.y), pk(v.z, v.w));
    }
}
// Transpose-pack all weights: W[K,512] fp32 -> Wt[512,K] fp16 regions.
struct WSrc { const float* w[8]; };
__global__ void pack_wT(WSrc ws, __half* __restrict__ out) {
    constexpr int R6 = 6 * 131072;            // 786432 (6 x 512*256)
    constexpr int R7 = R6 + 512 * 1024;       // 1310720
    constexpr int TOT = R7 + 512 * 512;       // 1572864
    for (int i = blockIdx.x * blockDim.x + threadIdx.x; i < TOT; i += gridDim.x * blockDim.x) {
        const float* W; int local, K;
        if (i < R6)      { W = ws.w[i / 131072]; local = i % 131072; K = 256; }
        else if (i < R7) { W = ws.w[6];          local = i - R6;     K = 1024; }
        else             { W = ws.w[7];          local = i - R7;     K = 512; }
        int n = local / K, k = local % K;
        out[i] = __float2half_rn(W[(size_t)k * 512 + n]);
    }
}

// =============================== GEMM =====================================
// C[M,512] = act( alpha * (A @ Wt^T) + bias ).  A fp16 [M,K] row-major,
// Wt fp16 [512,K] row-major. smem rows padded to 144 B (LDSM conflict-free).
// 128x128x64 tiles, 3-slot / 2-ahead cp.async stage pipeline PLUS an explicit
// register-level fragment pipeline: B rotates through a 2x4-reg buffer at nb
// granularity, A through a 2x8-reg buffer at kk granularity, so every LDSM's
// latency hides under the 4 MMAs consuming the previous fragment.
constexpr int ROWB = 144;                 // bytes per smem row (36 words)
constexpr int A_BYTES = 128 * ROWB;       // 18432
constexpr int STG_BYTES = 2 * A_BYTES;    // 36864 (A then B)
constexpr int NST = 3;
constexpr size_t GEMM_SMEM = (size_t)STG_BYTES * NST;   // 110592 B

template<typename TC, bool RELU, bool SPLITA, bool PROJ>
__global__ void __launch_bounds__(256, 2) gemm_l(
    const __half* __restrict__ A0, const __half* __restrict__ A1,
    const __half* __restrict__ Wt, const float* __restrict__ bias,
    TC* __restrict__ C, int K, int ksplit, int lda,
    size_t bstride, size_t cstride, float alpha0)
{
    extern __shared__ __align__(1024) uint8_t smem[];
    const uint32_t sb = (uint32_t)__cvta_generic_to_shared(smem);

    const int tid = threadIdx.x, w = tid >> 5, lane = tid & 31;
    const int bm = blockIdx.y * 128;
    const int bn = blockIdx.x * 128;
    const int bz = blockIdx.z;
    const __half* Az = PROJ ? (bz < 3 ? A0 : A1) : A0;
    const __half* Wz = Wt + (size_t)bz * bstride;
    TC* Cz = C + (size_t)bz * cstride;
    const float alpha = PROJ ? ((bz % 3 == 0) ? alpha0 : 1.0f) : alpha0;

    const int wm = (w & 3) * 32, wn = (w >> 2) * 64;
    const int lr = lane >> 2, lc = lane & 3;

    // per-lane LDSM base offsets (relative to stage base, bytes)
    const int lrow = lane & 15, lcol = (lane >> 4) * 16;
    const uint32_t aoff0 = (uint32_t)((wm + lrow) * ROWB + lcol);
    const uint32_t aoff1 = aoff0 + 16 * ROWB;
    const uint32_t boff0 = (uint32_t)(A_BYTES + (wn + lrow) * ROWB + lcol);

    float acc[2][8][4];
#pragma unroll
    for (int i = 0; i < 2; i++)
#pragma unroll
        for (int j = 0; j < 8; j++)
#pragma unroll
            for (int k = 0; k < 4; k++) acc[i][j][k] = 0.f;

    auto load_stage = [&](int s, int k0) {
        const __half* Ab = Az;
        int kl = k0;
        if (SPLITA && k0 >= ksplit) { Ab = A1; kl = k0 - ksplit; }
        uint32_t abase = sb + (uint32_t)s * STG_BYTES;
        uint32_t bbase = abase + A_BYTES;
#pragma unroll
        for (int i = 0; i < 4; i++) {
            int id = tid + i * 256;
            int r = id >> 3, q = id & 7;
            cpa16(abase + (uint32_t)(r * ROWB + q * 16),
                  Ab + (size_t)(bm + r) * lda + kl + q * 8);
        }
#pragma unroll
        for (int i = 0; i < 4; i++) {
            int id = tid + i * 256;
            int r = id >> 3, q = id & 7;
            cpa16(bbase + (uint32_t)(r * ROWB + q * 16),
                  Wz + (size_t)(bn + r) * K + k0 + q * 8);
        }
    };

    const int nt = K >> 6;
    load_stage(0, 0);  cpa_commit();
    load_stage(1, 64); cpa_commit();

    for (int t = 0; t < nt; t++) {
        cpa_wait<1>();
        __syncthreads();
        if (t + 2 < nt) load_stage((t + 2) % NST, (t + 2) << 6);
        cpa_commit();

        const uint32_t stg = sb + (uint32_t)(t % NST) * STG_BYTES;

        // ---- register-pipelined tile body ----
        uint32_t af[2][2][4];   // [kk parity][mi][4]
        uint32_t bf[2][4];      // [nb parity][4]
        ldsm4(af[0][0], stg + aoff0);
        ldsm4(af[0][1], stg + aoff1);
        ldsm4(bf[0],    stg + boff0);
#pragma unroll
        for (int kk = 0; kk < 4; kk++) {
            const int cur = kk & 1, nxt = cur ^ 1;
            const uint32_t kb = kk * 32;
            // prefetch A fragments for kk+1 (latency hides under this kk's MMAs)
            if (kk < 3) {
                ldsm4(af[nxt][0], stg + aoff0 + kb + 32);
                ldsm4(af[nxt][1], stg + aoff1 + kb + 32);
            }
#pragma unroll
            for (int nb = 0; nb < 4; nb++) {
                const int bcur = nb & 1, bnxt = bcur ^ 1;
                // prefetch next B fragment (next nb, or nb=0 of next kk)
                if (nb < 3)
                    ldsm4(bf[bnxt], stg + boff0 + (uint32_t)((nb + 1) * 16 * ROWB) + kb);
                else if (kk < 3)
                    ldsm4(bf[bnxt], stg + boff0 + kb + 32);
                mma16v(acc[0][2 * nb],
                       af[cur][0][0], af[cur][0][1], af[cur][0][2], af[cur][0][3],
                       bf[bcur][0], bf[bcur][2]);
                mma16v(acc[0][2 * nb + 1],
                       af[cur][0][0], af[cur][0][1], af[cur][0][2], af[cur][0][3],
                       bf[bcur][1], bf[bcur][3]);
                mma16v(acc[1][2 * nb],
                       af[cur][1][0], af[cur][1][1], af[cur][1][2], af[cur][1][3],
                       bf[bcur][0], bf[bcur][2]);
                mma16v(acc[1][2 * nb + 1],
                       af[cur][1][0], af[cur][1][1], af[cur][1][2], af[cur][1][3],
                       bf[bcur][1], bf[bcur][3]);
            }
        }
    }

    // epilogue (N fixed at 512)
#pragma unroll
    for (int mi = 0; mi < 2; mi++) {
#pragma unroll
        for (int ni = 0; ni < 8; ni++) {
            int row = bm + wm + mi * 16 + lr;
            int col = bn + wn + ni * 8 + lc * 2;
            float b0 = 0.f, b1 = 0.f;
            if (bias) { b0 = bias[col]; b1 = bias[col + 1]; }
            float v0 = acc[mi][ni][0] * alpha + b0;
            float v1 = acc[mi][ni][1] * alpha + b1;
            float v2 = acc[mi][ni][2] * alpha + b0;
            float v3 = acc[mi][ni][3] * alpha + b1;
            if (RELU) {
                v0 = fmaxf(v0, 0.f); v1 = fmaxf(v1, 0.f);
                v2 = fmaxf(v2, 0.f); v3 = fmaxf(v3, 0.f);
            }
            st2(Cz + (size_t)row * 512 + col, v0, v1);
            st2(Cz + (size_t)(row + 8) * 512 + col, v2, v3);
        }
    }
}

// ============================ Attention ===================================
// grid (2048, 2): y==0: a1 = softmax(q1 k2^T) v1 ; y==1: a2 = softmax(q2 k1^T) v2.
// O aliases V (per-column-chunk read-then-write, disjoint chunks).
constexpr int QW = 36, SLD = 68, VW = 72;
constexpr int QST = 64 * QW;   // 2304 words / stage
constexpr size_t ATTN_SMEM = (size_t)6 * QST * 4;   // 55296 B

__global__ void __launch_bounds__(256, 2) attn_kernel(
    const __half* __restrict__ q1, const __half* __restrict__ k1, __half* __restrict__ v1,
    const __half* __restrict__ q2, const __half* __restrict__ k2, __half* __restrict__ v2)
{
    extern __shared__ uint32_t asmem[];
    uint32_t* sQ = asmem;            // 3 stages Q; later S (fp32)
    uint32_t* sK = asmem + 3 * QST;  // 3 stages K; later P (stage0) + V (1,2)

    const int tid = threadIdx.x, w = tid >> 5, lane = tid & 31;
    const int lr = lane >> 2, lc = lane & 3;
    const int wm = (w & 3) * 16;
    const int wn = (w >> 2) * 32;
    const size_t base = (size_t)blockIdx.x * (64 * 512);

    const __half *Q, *Kx;  __half* V;
    if (blockIdx.y == 0) { Q = q1; Kx = k2; V = v1; }
    else                 { Q = q2; Kx = k1; V = v2; }
    __half* O = V;

    const uint32_t qsm = (uint32_t)__cvta_generic_to_shared(sQ);
    const uint32_t ksm = (uint32_t)__cvta_generic_to_shared(sK);

    // LDSM per-lane offsets (bytes, relative to stage base; row = 144 B)
    const int lrow = lane & 15, lcol = (lane >> 4) * 16;
    const uint32_t qoff = (uint32_t)((wm + lrow) * 144 + lcol);
    const uint32_t koff0 = (uint32_t)((wn + lrow) * 144 + lcol);
    const uint32_t koff1 = koff0 + 16 * 144;

    auto loadQK = [&](int st, int hc) {
#pragma unroll
        for (int i = 0; i < 2; i++) {
            int id = tid + i * 256;
            int r = id >> 3, q = id & 7;
            uint32_t off = (uint32_t)(st * QST + r * QW + q * 4) * 4;
            cpa16(qsm + off, Q  + base + (size_t)r * 512 + hc + q * 8);
            cpa16(ksm + off, Kx + base + (size_t)r * 512 + hc + q * 8);
        }
    };

    float sacc[4][4];
#pragma unroll
    for (int i = 0; i < 4; i++)
#pragma unroll
        for (int j = 0; j < 4; j++) sacc[i][j] = 0.f;

    loadQK(0, 0);   cpa_commit();
    loadQK(1, 64);  cpa_commit();
    for (int c = 0; c < 8; c++) {
        cpa_wait<1>();
        __syncthreads();
        if (c + 2 < 8) loadQK((c + 2) % 3, (c + 2) * 64);
        cpa_commit();

        const uint32_t qstg = qsm + (uint32_t)((c % 3) * QST) * 4;
        const uint32_t kstg = ksm + (uint32_t)((c % 3) * QST) * 4;
#pragma unroll
        for (int kk = 0; kk < 4; kk++) {
            const uint32_t kb = kk * 32;
            uint32_t af[4], kf0[4], kf1[4];
            ldsm4(af,  qstg + qoff  + kb);
            ldsm4(kf0, kstg + koff0 + kb);
            ldsm4(kf1, kstg + koff1 + kb);
            mma16v(sacc[0], af[0], af[1], af[2], af[3], kf0[0], kf0[2]);
            mma16v(sacc[1], af[0], af[1], af[2], af[3], kf0[1], kf0[3]);
            mma16v(sacc[2], af[0], af[1], af[2], af[3], kf1[0], kf1[2]);
            mma16v(sacc[3], af[0], af[1], af[2], af[3], kf1[1], kf1[3]);
        }
    }
    __syncthreads();

    float* S = reinterpret_cast<float*>(sQ);
#pragma unroll
    for (int ni = 0; ni < 4; ni++) {
        int row = wm + lr, col = wn + ni * 8 + lc * 2;
        S[row * SLD + col]           = sacc[ni][0];
        S[row * SLD + col + 1]       = sacc[ni][1];
        S[(row + 8) * SLD + col]     = sacc[ni][2];
        S[(row + 8) * SLD + col + 1] = sacc[ni][3];
    }
    __syncthreads();

    for (int r = w * 8; r < w * 8 + 8; r++) {
        float v0 = S[r * SLD + lane], v1 = S[r * SLD + 32 + lane];
        float m = fmaxf(v0, v1);
#pragma unroll
        for (int o = 16; o > 0; o >>= 1) m = fmaxf(m, __shfl_xor_sync(0xffffffffu, m, o));
        float e0 = __expf(v0 - m), e1 = __expf(v1 - m);
        float s = e0 + e1;
#pragma unroll
        for (int o = 16; o > 0; o >>= 1) s += __shfl_xor_sync(0xffffffffu, s, o);
        float inv = 1.f / s;
        S[r * SLD + lane]      = e0 * inv;
        S[r * SLD + 32 + lane] = e1 * inv;
    }
    __syncthreads();

    uint32_t* Pw = sK;
    for (int idx = tid; idx < 64 * 32; idx += 256) {
        int row = idx >> 5, mp = idx & 31;
        Pw[row * QW + mp] = pk(S[row * SLD + 2 * mp], S[row * SLD + 2 * mp + 1]);
    }
    __syncthreads();

    uint32_t paf[4][4];
#pragma unroll
    for (int c = 0; c < 4; c++) {
        int kk2 = c * 8, r0 = wm + lr;
        paf[c][0] = Pw[r0 * QW + kk2 + lc];
        paf[c][1] = Pw[(r0 + 8) * QW + kk2 + lc];
        paf[c][2] = Pw[r0 * QW + kk2 + lc + 4];
        paf[c][3] = Pw[(r0 + 8) * QW + kk2 + lc + 4];
    }
    __syncthreads();

    const int mp0 = tid >> 4, h40 = (tid & 15) * 4;
    const int mp1 = (tid + 256) >> 4, h41 = ((tid + 256) & 15) * 4;

    uint2 ra0, rb0, ra1, rb1;
    auto ldV = [&](int hc) {
        ra0 = *reinterpret_cast<const uint2*>(V + base + (size_t)(2 * mp0) * 512 + hc + h40);
        rb0 = *reinterpret_cast<const uint2*>(V + base + (size_t)(2 * mp0 + 1) * 512 + hc + h40);
        ra1 = *reinterpret_cast<const uint2*>(V + base + (size_t)(2 * mp1) * 512 + hc + h41);
        rb1 = *reinterpret_cast<const uint2*>(V + base + (size_t)(2 * mp1 + 1) * 512 + hc + h41);
    };
    ldV(0);

    for (int ci = 0; ci < 8; ci++) {
        int hc = ci * 64;
        uint32_t* vb = sK + (1 + (ci & 1)) * QST;
        *reinterpret_cast<uint4*>(&vb[mp0 * VW + h40]) =
            make_uint4(__byte_perm(ra0.x, rb0.x, 0x5410), __byte_perm(ra0.x, rb0.x, 0x7632),
                       __byte_perm(ra0.y, rb0.y, 0x5410), __byte_perm(ra0.y, rb0.y, 0x7632));
        *reinterpret_cast<uint4*>(&vb[mp1 * VW + h41]) =
            make_uint4(__byte_perm(ra1.x, rb1.x, 0x5410), __byte_perm(ra1.x, rb1.x, 0x7632),
                       __byte_perm(ra1.y, rb1.y, 0x5410), __byte_perm(ra1.y, rb1.y, 0x7632));
        __syncthreads();

        if (ci + 1 < 8) ldV(hc + 64);

        float oacc[4][4];
#pragma unroll
        for (int i = 0; i < 4; i++)
#pragma unroll
            for (int j = 0; j < 4; j++) oacc[i][j] = 0.f;
#pragma unroll
        for (int c = 0; c < 4; c++) {
            int kk2 = c * 8;
#pragma unroll
            for (int ni = 0; ni < 4; ni++) {
                int c0 = wn + ni * 8 + lr;
                mma16v(oacc[ni], paf[c][0], paf[c][1], paf[c][2], paf[c][3],
                       vb[(kk2 + lc) * VW + c0], vb[(kk2 + lc + 4) * VW + c0]);
            }
        }
#pragma unroll
        for (int ni = 0; ni < 4; ni++) {
            int row = wm + lr, col = wn + ni * 8 + lc * 2;
            st2(O + base + (size_t)row * 512 + hc + col,       oacc[ni][0], oacc[ni][1]);
            st2(O + base + (size_t)(row + 8) * 512 + hc + col, oacc[ni][2], oacc[ni][3]);
        }
    }
}

// ============================== launch ====================================
extern "C" void kernel_launch(void* const* d_in, const int* in_sizes, int n_in,
                              void* d_out, int out_size)
{
    const float* x1  = (const float*)d_in[0];
    const float* x2  = (const float*)d_in[1];
    const float* b1  = (const float*)d_in[9];
    const float* b2  = (const float*)d_in[11];
    float* out = (float*)d_out;

    __half* s;  __half* wbase;
    cudaGetSymbolAddress((void**)&s, g_h);
    cudaGetSymbolAddress((void**)&wbase, g_w);

    __half* q1 = s + 0 * BUF;
    __half* k1 = s + 1 * BUF;
    __half* v1 = s + 2 * BUF;
    __half* q2 = s + 3 * BUF;
    __half* k2 = s + 4 * BUF;
    __half* v2 = s + 5 * BUF;
    __half* xh1 = s + 6 * BUF;
    __half* xh2 = xh1 + XBUF;
    __half* a1 = v1;   // attention output aliases V
    __half* a2 = v2;
    __half* h  = q1;   // MLP hidden reuses q1

    __half* wqkvT = wbase;                    // 6 x (512*256), z-major
    __half* w1T   = wbase + 6 * 131072;       // 512*1024
    __half* w2T   = w1T + 512 * 1024;         // 512*512

    const float scale = 0.0625f;  // 256^-0.5
    dim3 blk(256);

    cudaFuncSetAttribute(gemm_l<__half, false, false, true >, cudaFuncAttributeMaxDynamicSharedMemorySize, (int)GEMM_SMEM);
    cudaFuncSetAttribute(gemm_l<__half, true,  true,  false>, cudaFuncAttributeMaxDynamicSharedMemorySize, (int)GEMM_SMEM);
    cudaFuncSetAttribute(gemm_l<float,  false, false, false>, cudaFuncAttributeMaxDynamicSharedMemorySize, (int)GEMM_SMEM);
    cudaFuncSetAttribute(attn_kernel, cudaFuncAttributeMaxDynamicSharedMemorySize, (int)ATTN_SMEM);

    // ---- pre-pass: fp16 x copies + transposed fp16 weights ----
    cvt_f2h<<<4096, 256>>>(x1, xh1, (int)(XBUF / 4));
    cvt_f2h<<<4096, 256>>>(x2, xh2, (int)(XBUF / 4));
    WSrc ws;
    ws.w[0] = (const float*)d_in[2];  // Wq1
    ws.w[1] = (const float*)d_in[3];  // Wk1
    ws.w[2] = (const float*)d_in[4];  // Wv1
    ws.w[3] = (const float*)d_in[5];  // Wq2
    ws.w[4] = (const float*)d_in[6];  // Wk2
    ws.w[5] = (const float*)d_in[7];  // Wv2
    ws.w[6] = (const float*)d_in[8];  // W1
    ws.w[7] = (const float*)d_in[10]; // W2
    pack_wT<<<2048, 256>>>(ws, wbase);

    // ---- stage 1: all 6 projections in ONE launch (z: 0..5) ----
    dim3 gproj(4, MROWS / 128, 6);
    gemm_l<__half, false, false, true><<<gproj, blk, GEMM_SMEM>>>(
        xh1, xh2, wqkvT, nullptr, q1, D_, 0, D_, 131072, BUF, scale);

    // ---- stage 2: both cross attentions in ONE launch ----
    attn_kernel<<<dim3(BT, 2), blk, ATTN_SMEM>>>(q1, k1, v1, q2, k2, v2);

    // ---- stage 3: MLP ----
    dim3 gmlp(4, MROWS / 128, 1);
    gemm_l<__half, true, true, false><<<gmlp, blk, GEMM_SMEM>>>(
        a1, a2, w1T, b1, h, 2 * H_, H_, H_, 0, 0, 1.f);
    gemm_l<float, false, false, false><<<gmlp, blk, GEMM_SMEM>>>(
        h, nullptr, w2T, b2, out, H_, 0, H_, 0, 0, 1.f);
}

// round 14
// speedup vs baseline: 1.2483x; 1.2328x over previous
#include <cuda_runtime.h>
#include <cuda_fp16.h>
#include <cstdint>

// Problem constants
constexpr int B_ = 16, T_ = 128, N_ = 64, D_ = 256, H_ = 512;
constexpr int MROWS = B_ * T_ * N_;          // 131072 flattened rows
constexpr int BT   = B_ * T_;                // 2048 attention problems

// ---------------- scratch (device globals) ---------------------------------
// Layout (halves): buf1 [M,768] | buf2 [M,768] | xh1 [M,256] | xh2 [M,256] | h [M,512]
__device__ __align__(16) __half g_h[(size_t)MROWS * 2560];
// packed fp16x2 weight words: wcomb 2x(128x768)=196608, w1p 512x512=262144, w2p 131072
__device__ __align__(16) uint32_t g_w[589824];
// fp32 temp for M1, M2 (256x256 each)
__device__ __align__(16) float g_mt[2 * 65536];

__device__ __forceinline__ uint32_t pk(float a, float b) {
    __half2 h = __floats2half2_rn(a, b);
    return *reinterpret_cast<uint32_t*>(&h);
}
__device__ __forceinline__ void st2(float* p, float v0, float v1) {
    *reinterpret_cast<float2*>(p) = make_float2(v0, v1);
}
__device__ __forceinline__ void st2(__half* p, float v0, float v1) {
    *reinterpret_cast<__half2*>(p) = __floats2half2_rn(v0, v1);
}

// mma.sync m16n8k16 fp16 in / fp32 accum
__device__ __forceinline__ void mma16v(float* d,
    uint32_t a0, uint32_t a1, uint32_t a2, uint32_t a3,
    uint32_t b0, uint32_t b1) {
    asm volatile(
        "mma.sync.aligned.m16n8k16.row.col.f32.f16.f16.f32 "
        "{%0,%1,%2,%3}, {%4,%5,%6,%7}, {%8,%9}, {%0,%1,%2,%3};"
        : "+f"(d[0]), "+f"(d[1]), "+f"(d[2]), "+f"(d[3])
        : "r"(a0), "r"(a1), "r"(a2), "r"(a3), "r"(b0), "r"(b1));
}

__device__ __forceinline__ void cpa16(uint32_t dst_smem, const void* src) {
    asm volatile("cp.async.cg.shared.global [%0], [%1], 16;" :: "r"(dst_smem), "l"(src));
}
__device__ __forceinline__ void cpa_commit() { asm volatile("cp.async.commit_group;"); }
template<int Ngrp> __device__ __forceinline__ void cpa_wait() {
    asm volatile("cp.async.wait_group %0;" :: "n"(Ngrp));
}

// ======================= pre-pass kernels =================================
__global__ void cvt_f2h(const float* __restrict__ src, __half* __restrict__ dst, int n4) {
    for (int i = blockIdx.x * blockDim.x + threadIdx.x; i < n4; i += gridDim.x * blockDim.x) {
        float4 v = reinterpret_cast<const float4*>(src)[i];
        reinterpret_cast<uint2*>(dst)[i] = make_uint2(pk(v.x, v.y), pk(v.z, v.w));
    }
}

// M1 = scale * Wq1 @ Wk2^T ; M2 = scale * Wq2 @ Wk1^T  (all [256,512] inputs, fp32)
__global__ void compute_M(const float* __restrict__ Wq1, const float* __restrict__ Wk2,
                          const float* __restrict__ Wq2, const float* __restrict__ Wk1,
                          float* __restrict__ Mt) {
    const int d = blockIdx.x, s = blockIdx.y, e = threadIdx.x;
    const float* Wq = s ? Wq2 : Wq1;
    const float* Wk = s ? Wk1 : Wk2;
    __shared__ float4 qrow[128];
    for (int i = threadIdx.x; i < 128; i += 256)
        qrow[i] = reinterpret_cast<const float4*>(Wq + (size_t)d * 512)[i];
    __syncthreads();
    const float4* wk = reinterpret_cast<const float4*>(Wk + (size_t)e * 512);
    float acc = 0.f;
#pragma unroll 8
    for (int i = 0; i < 128; i++) {
        float4 q = qrow[i], w = wk[i];
        acc += q.x * w.x + q.y * w.y + q.z * w.z + q.w * w.w;
    }
    Mt[s * 65536 + d * 256 + e] = acc * 0.0625f;   // scale = 256^-0.5
}

// Pack all GEMM B operands as k-pair fp16x2 words.
// wcomb slice s: [128 kp][768 n]: n<256 -> M_s[k][n]; n>=256 -> Wv_s[k][n-256]
struct PSrc { const float* wv1; const float* wv2; const float* w1; const float* w2; };
__global__ void pack_all(PSrc p, const float* __restrict__ Mt, uint32_t* __restrict__ out) {
    constexpr int RC = 2 * 128 * 768;        // 196608
    constexpr int R1 = RC + 512 * 512;       // 458752
    constexpr int TOT = R1 + 256 * 512;      // 589824
    for (int i = blockIdx.x * blockDim.x + threadIdx.x; i < TOT; i += gridDim.x * blockDim.x) {
        if (i < RC) {
            int s = i / 98304, local = i % 98304;
            int kp = local / 768, n = local % 768;
            float lo, hi;
            if (n < 256) {
                lo = Mt[s * 65536 + (2 * kp) * 256 + n];
                hi = Mt[s * 65536 + (2 * kp + 1) * 256 + n];
            } else {
                const float* Wv = s ? p.wv2 : p.wv1;
                lo = Wv[(size_t)(2 * kp) * 512 + (n - 256)];
                hi = Wv[(size_t)(2 * kp + 1) * 512 + (n - 256)];
            }
            out[i] = pk(lo, hi);
        } else if (i < R1) {
            int j = i - RC; int kp = j >> 9, n = j & 511;
            out[i] = pk(p.w1[(size_t)(2 * kp) * 512 + n], p.w1[(size_t)(2 * kp + 1) * 512 + n]);
        } else {
            int j = i - R1; int kp = j >> 9, n = j & 511;
            out[i] = pk(p.w2[(size_t)(2 * kp) * 512 + n], p.w2[(size_t)(2 * kp + 1) * 512 + n]);
        }
    }
}

// =============================== GEMM =====================================
// C[M,N] = act( alpha * (A @ B) + bias ).  A fp16 row-major [M,K] (lda),
// B pre-packed u32 k-pair words [K/2][N]. 128x128x64 tiles, 3-stage cp.async
// pipeline (prefetch distance 2), 256 thr, 8 warps (4m x 2n). R8-proven body.
constexpr int AW = 36, BW = 136;          // smem strides (words)
constexpr int A_ST = 128 * AW;            // 4608 words
constexpr int B_ST = 32 * BW;             // 4352 words
constexpr int ST_W = A_ST + B_ST;         // 8960 words / stage
constexpr int NST = 3;
constexpr size_t GEMM_SMEM = (size_t)ST_W * NST * 4;   // 107520 B

template<typename TC, bool RELU, bool SPLITA, bool PROJ>
__global__ void __launch_bounds__(256, 2) gemm_p(
    const __half* __restrict__ A0, const __half* __restrict__ A1,
    const uint32_t* __restrict__ Bp, const float* __restrict__ bias,
    TC* __restrict__ C, int K, int ksplit, int lda,
    size_t bstride, size_t cstride, float alpha, int N)
{
    extern __shared__ uint32_t smem[];
    const uint32_t sm_base = (uint32_t)__cvta_generic_to_shared(smem);

    const int tid = threadIdx.x;
    const int bm  = blockIdx.y * 128;
    const int bn  = blockIdx.x * 128;
    const int bz  = blockIdx.z;
    const __half*   Az = PROJ ? (bz ? A1 : A0) : A0;
    const uint32_t* Bz = Bp + (size_t)bz * bstride;
    TC* Cz = C + (size_t)bz * cstride;

    const int w = tid >> 5, lane = tid & 31;
    const int wm = (w & 3) * 32, wn = (w >> 2) * 64;
    const int lr = lane >> 2, lc = lane & 3;

    float acc[2][8][4];
#pragma unroll
    for (int i = 0; i < 2; i++)
#pragma unroll
        for (int j = 0; j < 8; j++)
#pragma unroll
            for (int k = 0; k < 4; k++) acc[i][j][k] = 0.f;

    auto load_stage = [&](int s, int k0) {
        const __half* Ab = Az;
        int kl = k0;
        if (SPLITA && k0 >= ksplit) { Ab = A1; kl = k0 - ksplit; }
        uint32_t abase = sm_base + (uint32_t)(s * ST_W) * 4;
        uint32_t bbase = abase + (uint32_t)A_ST * 4;
#pragma unroll
        for (int i = 0; i < 4; i++) {
            int id = tid + i * 256;
            int r = id >> 3, q = id & 7;
            cpa16(abase + (uint32_t)(r * AW + q * 4) * 4,
                  Ab + (size_t)(bm + r) * lda + kl + q * 8);
        }
#pragma unroll
        for (int i = 0; i < 4; i++) {
            int id = tid + i * 256;
            int kp = id >> 5, j = id & 31;
            cpa16(bbase + (uint32_t)(kp * BW + j * 4) * 4,
                  Bz + (size_t)((k0 >> 1) + kp) * N + bn + j * 4);
        }
    };

    const int nt = K >> 6;
    load_stage(0, 0);  cpa_commit();
    if (nt > 1) load_stage(1, 64);
    cpa_commit();

    for (int t = 0; t < nt; t++) {
        cpa_wait<1>();
        __syncthreads();
        int tn = t + 2;
        if (tn < nt) load_stage(tn % NST, tn << 6);
        cpa_commit();

        const uint32_t* Ast = smem + (t % NST) * ST_W;
        const uint32_t* Bst = Ast + A_ST;
#pragma unroll
        for (int kk2 = 0; kk2 < 32; kk2 += 8) {
            uint32_t af[2][4];
#pragma unroll
            for (int mi = 0; mi < 2; mi++) {
                int r0 = wm + mi * 16 + lr;
                af[mi][0] = Ast[r0 * AW + kk2 + lc];
                af[mi][1] = Ast[(r0 + 8) * AW + kk2 + lc];
                af[mi][2] = Ast[r0 * AW + kk2 + lc + 4];
                af[mi][3] = Ast[(r0 + 8) * AW + kk2 + lc + 4];
            }
            uint32_t bf[8][2];
#pragma unroll
            for (int ni = 0; ni < 8; ni++) {
                int c0 = wn + ni * 8 + lr;
                bf[ni][0] = Bst[(kk2 + lc) * BW + c0];
                bf[ni][1] = Bst[(kk2 + lc + 4) * BW + c0];
            }
#pragma unroll
            for (int mi = 0; mi < 2; mi++)
#pragma unroll
                for (int ni = 0; ni < 8; ni++)
                    mma16v(acc[mi][ni],
                           af[mi][0], af[mi][1], af[mi][2], af[mi][3],
                           bf[ni][0], bf[ni][1]);
        }
        __syncthreads();
    }

    // epilogue
#pragma unroll
    for (int mi = 0; mi < 2; mi++) {
#pragma unroll
        for (int ni = 0; ni < 8; ni++) {
            int row = bm + wm + mi * 16 + lr;
            int col = bn + wn + ni * 8 + lc * 2;
            float b0 = 0.f, b1 = 0.f;
            if (bias) { b0 = bias[col]; b1 = bias[col + 1]; }
            float v0 = acc[mi][ni][0] * alpha + b0;
            float v1 = acc[mi][ni][1] * alpha + b1;
            float v2 = acc[mi][ni][2] * alpha + b0;
            float v3 = acc[mi][ni][3] * alpha + b1;
            if (RELU) {
                v0 = fmaxf(v0, 0.f); v1 = fmaxf(v1, 0.f);
                v2 = fmaxf(v2, 0.f); v3 = fmaxf(v3, 0.f);
            }
            st2(Cz + (size_t)row * N + col, v0, v1);
            st2(Cz + (size_t)(row + 8) * N + col, v2, v3);
        }
    }
}

// ============================ Attention ===================================
// grid (2048, 2).
//   y==0: S = xm1 @ xh2^T (contraction 256), a1 = softmax(S) @ v1
//   y==1: S = xm2 @ xh1^T,                   a2 = softmax(S) @ v2
// Q = slice buffer cols [0,256) stride 768; K = xh stride 256;
// V = O = slice buffer cols [256,768) stride 768 (aliased, chunk-safe).
constexpr int QW = 36, SLD = 68, VW = 72;
constexpr int QST = 64 * QW;   // 2304 words / stage
constexpr size_t ATTN_SMEM = (size_t)6 * QST * 4;   // 55296 B

__global__ void __launch_bounds__(256, 2) attn_kernel(
    __half* __restrict__ buf1, __half* __restrict__ buf2,
    const __half* __restrict__ xh1, const __half* __restrict__ xh2)
{
    extern __shared__ uint32_t asmem[];
    uint32_t* sQ = asmem;            // 3 stages Q; later S (fp32)
    uint32_t* sK = asmem + 3 * QST;  // 3 stages K; later P (stage0) + V (1,2)

    const int tid = threadIdx.x, w = tid >> 5, lane = tid & 31;
    const int lr = lane >> 2, lc = lane & 3;
    const int wm = (w & 3) * 16;
    const int wn = (w >> 2) * 32;

    const __half* Q; const __half* Kx; __half* V;
    if (blockIdx.y == 0) { Q = buf1; Kx = xh2; V = buf1 + 256; }
    else                 { Q = buf2; Kx = xh1; V = buf2 + 256; }
    __half* O = V;
    const size_t qbase = (size_t)blockIdx.x * 64 * 768;
    const size_t kbase = (size_t)blockIdx.x * 64 * 256;

    const uint32_t qsm = (uint32_t)__cvta_generic_to_shared(sQ);
    const uint32_t ksm = (uint32_t)__cvta_generic_to_shared(sK);

    auto loadQK = [&](int st, int hc) {
#pragma unroll
        for (int i = 0; i < 2; i++) {
            int id = tid + i * 256;
            int r = id >> 3, q = id & 7;
            uint32_t off = (uint32_t)(st * QST + r * QW + q * 4) * 4;
            cpa16(qsm + off, Q  + qbase + (size_t)r * 768 + hc + q * 8);
            cpa16(ksm + off, Kx + kbase + (size_t)r * 256 + hc + q * 8);
        }
    };

    float sacc[4][4];
#pragma unroll
    for (int i = 0; i < 4; i++)
#pragma unroll
        for (int j = 0; j < 4; j++) sacc[i][j] = 0.f;

    // ---- Phase 1: S = xm @ xh^T over 256, 4 chunks of 64, pipelined ----
    loadQK(0, 0);   cpa_commit();
    loadQK(1, 64);  cpa_commit();
    for (int c = 0; c < 4; c++) {
        cpa_wait<1>();
        __syncthreads();
        if (c + 2 < 4) loadQK((c + 2) % 3, (c + 2) * 64);
        cpa_commit();

        const uint32_t* qb = sQ + (c % 3) * QST;
        const uint32_t* kb = sK + (c % 3) * QST;
#pragma unroll
        for (int kk2 = 0; kk2 < 32; kk2 += 8) {
            uint32_t af[4];
            int r0 = wm + lr;
            af[0] = qb[r0 * QW + kk2 + lc];
            af[1] = qb[(r0 + 8) * QW + kk2 + lc];
            af[2] = qb[r0 * QW + kk2 + lc + 4];
            af[3] = qb[(r0 + 8) * QW + kk2 + lc + 4];
#pragma unroll
            for (int ni = 0; ni < 4; ni++) {
                int c0 = wn + ni * 8 + lr;
                mma16v(sacc[ni], af[0], af[1], af[2], af[3],
                       kb[c0 * QW + kk2 + lc], kb[c0 * QW + kk2 + lc + 4]);
            }
        }
    }
    __syncthreads();

    // ---- dump S (fp32) into sQ ----
    float* S = reinterpret_cast<float*>(sQ);
#pragma unroll
    for (int ni = 0; ni < 4; ni++) {
        int row = wm + lr, col = wn + ni * 8 + lc * 2;
        S[row * SLD + col]           = sacc[ni][0];
        S[row * SLD + col + 1]       = sacc[ni][1];
        S[(row + 8) * SLD + col]     = sacc[ni][2];
        S[(row + 8) * SLD + col + 1] = sacc[ni][3];
    }
    __syncthreads();

    // ---- Phase 2: softmax (fp32), each warp owns 8 rows ----
    for (int r = w * 8; r < w * 8 + 8; r++) {
        float v0 = S[r * SLD + lane], v1 = S[r * SLD + 32 + lane];
        float m = fmaxf(v0, v1);
#pragma unroll
        for (int o = 16; o > 0; o >>= 1) m = fmaxf(m, __shfl_xor_sync(0xffffffffu, m, o));
        float e0 = __expf(v0 - m), e1 = __expf(v1 - m);
        float s = e0 + e1;
#pragma unroll
        for (int o = 16; o > 0; o >>= 1) s += __shfl_xor_sync(0xffffffffu, s, o);
        float inv = 1.f / s;
        S[r * SLD + lane]      = e0 * inv;
        S[r * SLD + 32 + lane] = e1 * inv;
    }
    __syncthreads();

    // ---- pack P (fp16 pair-words) into sK stage 0 ----
    uint32_t* Pw = sK;
    for (int idx = tid; idx < 64 * 32; idx += 256) {
        int row = idx >> 5, mp = idx & 31;
        Pw[row * QW + mp] = pk(S[row * SLD + 2 * mp], S[row * SLD + 2 * mp + 1]);
    }
    __syncthreads();

    // ---- hoist P fragments (reused for all 8 h-chunks) ----
    uint32_t paf[4][4];
#pragma unroll
    for (int c = 0; c < 4; c++) {
        int kk2 = c * 8, r0 = wm + lr;
        paf[c][0] = Pw[r0 * QW + kk2 + lc];
        paf[c][1] = Pw[(r0 + 8) * QW + kk2 + lc];
        paf[c][2] = Pw[r0 * QW + kk2 + lc + 4];
        paf[c][3] = Pw[(r0 + 8) * QW + kk2 + lc + 4];
    }
    __syncthreads();   // sK free for V stages

    // ---- Phase 3: O = P @ V, reg-pipelined V loads, 2-stage smem ----
    const int mp0 = tid >> 4, h40 = (tid & 15) * 4;
    const int mp1 = (tid + 256) >> 4, h41 = ((tid + 256) & 15) * 4;

    uint2 ra0, rb0, ra1, rb1;
    auto ldV = [&](int hc) {
        ra0 = *reinterpret_cast<const uint2*>(V + qbase + (size_t)(2 * mp0) * 768 + hc + h40);
        rb0 = *reinterpret_cast<const uint2*>(V + qbase + (size_t)(2 * mp0 + 1) * 768 + hc + h40);
        ra1 = *reinterpret_cast<const uint2*>(V + qbase + (size_t)(2 * mp1) * 768 + hc + h41);
        rb1 = *reinterpret_cast<const uint2*>(V + qbase + (size_t)(2 * mp1 + 1) * 768 + hc + h41);
    };
    ldV(0);

    for (int ci = 0; ci < 8; ci++) {
        int hc = ci * 64;
        uint32_t* vb = sK + (1 + (ci & 1)) * QST;   // stages 1,2
        *reinterpret_cast<uint4*>(&vb[mp0 * VW + h40]) =
            make_uint4(__byte_perm(ra0.x, rb0.x, 0x5410), __byte_perm(ra0.x, rb0.x, 0x7632),
                       __byte_perm(ra0.y, rb0.y, 0x5410), __byte_perm(ra0.y, rb0.y, 0x7632));
        *reinterpret_cast<uint4*>(&vb[mp1 * VW + h41]) =
            make_uint4(__byte_perm(ra1.x, rb1.x, 0x5410), __byte_perm(ra1.x, rb1.x, 0x7632),
                       __byte_perm(ra1.y, rb1.y, 0x5410), __byte_perm(ra1.y, rb1.y, 0x7632));
        __syncthreads();

        if (ci + 1 < 8) ldV(hc + 64);  // prefetch next chunk

        float oacc[4][4];
#pragma unroll
        for (int i = 0; i < 4; i++)
#pragma unroll
            for (int j = 0; j < 4; j++) oacc[i][j] = 0.f;
#pragma unroll
        for (int c = 0; c < 4; c++) {
            int kk2 = c * 8;
#pragma unroll
            for (int ni = 0; ni < 4; ni++) {
                int c0 = wn + ni * 8 + lr;
                mma16v(oacc[ni], paf[c][0], paf[c][1], paf[c][2], paf[c][3],
                       vb[(kk2 + lc) * VW + c0], vb[(kk2 + lc + 4) * VW + c0]);
            }
        }
#pragma unroll
        for (int ni = 0; ni < 4; ni++) {
            int row = wm + lr, col = wn + ni * 8 + lc * 2;
            st2(O + qbase + (size_t)row * 768 + hc + col,       oacc[ni][0], oacc[ni][1]);
            st2(O + qbase + (size_t)(row + 8) * 768 + hc + col, oacc[ni][2], oacc[ni][3]);
        }
        __syncthreads();
    }
}

// ============================== launch ====================================
extern "C" void kernel_launch(void* const* d_in, const int* in_sizes, int n_in,
                              void* d_out, int out_size)
{
    const float* x1  = (const float*)d_in[0];
    const float* x2  = (const float*)d_in[1];
    const float* Wq1 = (const float*)d_in[2];
    const float* Wk1 = (const float*)d_in[3];
    const float* Wv1 = (const float*)d_in[4];
    const float* Wq2 = (const float*)d_in[5];
    const float* Wk2 = (const float*)d_in[6];
    const float* Wv2 = (const float*)d_in[7];
    const float* W1  = (const float*)d_in[8];
    const float* b1  = (const float*)d_in[9];
    const float* W2  = (const float*)d_in[10];
    const float* b2  = (const float*)d_in[11];
    float* out = (float*)d_out;

    __half* s;  uint32_t* wbase;  float* mt;
    cudaGetSymbolAddress((void**)&s, g_h);
    cudaGetSymbolAddress((void**)&wbase, g_w);
    cudaGetSymbolAddress((void**)&mt, g_mt);

    __half* buf1 = s;                                 // [M,768]: xm1 | v1/a1
    __half* buf2 = s + (size_t)MROWS * 768;           // [M,768]: xm2 | v2/a2
    __half* xh1  = s + (size_t)MROWS * 1536;          // [M,256]
    __half* xh2  = xh1 + (size_t)MROWS * 256;
    __half* h    = s + (size_t)MROWS * 2048;          // [M,512] MLP hidden

    uint32_t* wcomb = wbase;                          // 2 x (128*768)
    uint32_t* w1p   = wbase + 196608;                 // 512*512
    uint32_t* w2p   = wbase + 458752;                 // 256*512

    dim3 blk(256);

    cudaFuncSetAttribute(gemm_p<__half, false, false, true >, cudaFuncAttributeMaxDynamicSharedMemorySize, (int)GEMM_SMEM);
    cudaFuncSetAttribute(gemm_p<__half, true,  true,  false>, cudaFuncAttributeMaxDynamicSharedMemorySize, (int)GEMM_SMEM);
    cudaFuncSetAttribute(gemm_p<float,  false, false, false>, cudaFuncAttributeMaxDynamicSharedMemorySize, (int)GEMM_SMEM);
    cudaFuncSetAttribute(attn_kernel, cudaFuncAttributeMaxDynamicSharedMemorySize, (int)ATTN_SMEM);

    // ---- pre-pass ----
    cvt_f2h<<<4096, 256>>>(x1, xh1, MROWS * 256 / 4);
    cvt_f2h<<<4096, 256>>>(x2, xh2, MROWS * 256 / 4);
    compute_M<<<dim3(256, 2), 256>>>(Wq1, Wk2, Wq2, Wk1, mt);
    PSrc ps; ps.wv1 = Wv1; ps.wv2 = Wv2; ps.w1 = W1; ps.w2 = W2;
    pack_all<<<1024, 256>>>(ps, mt, wbase);

    // ---- stage 1: fused [xm | v] projections, 2 slices, N=768 ----
    dim3 gproj(6, MROWS / 128, 2);
    gemm_p<__half, false, false, true><<<gproj, blk, GEMM_SMEM>>>(
        xh1, xh2, wcomb, nullptr, buf1, 256, 0, 256,
        98304, (size_t)MROWS * 768, 1.f, 768);

    // ---- stage 2: both cross attentions ----
    attn_kernel<<<dim3(BT, 2), blk, ATTN_SMEM>>>(buf1, buf2, xh1, xh2);

    // ---- stage 3: MLP ----
    dim3 gmlp(4, MROWS / 128, 1);
    gemm_p<__half, true, true, false><<<gmlp, blk, GEMM_SMEM>>>(
        buf1 + 256, buf2 + 256, w1p, b1, h, 1024, 512, 768, 0, 0, 1.f, 512);
    gemm_p<float, false, false, false><<<gmlp, blk, GEMM_SMEM>>>(
        h, nullptr, w2p, b2, out, 512, 0, 512, 0, 0, 1.f, 512);
}

// round 16
// speedup vs baseline: 1.2649x; 1.0133x over previous
#include <cuda_runtime.h>
#include <cuda_fp16.h>
#include <cstdint>

// Problem constants
constexpr int B_ = 16, T_ = 128, N_ = 64, D_ = 256, H_ = 512;
constexpr int MROWS = B_ * T_ * N_;          // 131072 flattened rows
constexpr int BT   = B_ * T_;                // 2048 attention problems

// ---------------- scratch (device globals) ---------------------------------
// Layout (halves): buf1 [M,768] | buf2 [M,768] | xh1 [M,256] | xh2 [M,256] | h [M,512]
__device__ __align__(16) __half g_h[(size_t)MROWS * 2560];
// packed fp16x2 weight words: wcomb 2x(128x768)=196608, w1p 512x512=262144, w2p 131072
__device__ __align__(16) uint32_t g_w[589824];
// fp32 temp for M1, M2 (256x256 each)
__device__ __align__(16) float g_mt[2 * 65536];

__device__ __forceinline__ uint32_t pk(float a, float b) {
    __half2 h = __floats2half2_rn(a, b);
    return *reinterpret_cast<uint32_t*>(&h);
}
__device__ __forceinline__ void st2(float* p, float v0, float v1) {
    *reinterpret_cast<float2*>(p) = make_float2(v0, v1);
}
__device__ __forceinline__ void st2(__half* p, float v0, float v1) {
    *reinterpret_cast<__half2*>(p) = __floats2half2_rn(v0, v1);
}

// mma.sync m16n8k16 fp16 in / fp32 accum
__device__ __forceinline__ void mma16v(float* d,
    uint32_t a0, uint32_t a1, uint32_t a2, uint32_t a3,
    uint32_t b0, uint32_t b1) {
    asm volatile(
        "mma.sync.aligned.m16n8k16.row.col.f32.f16.f16.f32 "
        "{%0,%1,%2,%3}, {%4,%5,%6,%7}, {%8,%9}, {%0,%1,%2,%3};"
        : "+f"(d[0]), "+f"(d[1]), "+f"(d[2]), "+f"(d[3])
        : "r"(a0), "r"(a1), "r"(a2), "r"(a3), "r"(b0), "r"(b1));
}

__device__ __forceinline__ void cpa16(uint32_t dst_smem, const void* src) {
    asm volatile("cp.async.cg.shared.global [%0], [%1], 16;" :: "r"(dst_smem), "l"(src));
}
__device__ __forceinline__ void cpa_commit() { asm volatile("cp.async.commit_group;"); }
template<int Ngrp> __device__ __forceinline__ void cpa_wait() {
    asm volatile("cp.async.wait_group %0;" :: "n"(Ngrp));
}

// ======================= pre-pass kernels =================================
// Convert BOTH x tensors fp32 -> fp16 in one launch.
__global__ void cvt_f2h2(const float* __restrict__ s0, __half* __restrict__ d0,
                         const float* __restrict__ s1, __half* __restrict__ d1, int n4) {
    for (int i = blockIdx.x * blockDim.x + threadIdx.x; i < 2 * n4; i += gridDim.x * blockDim.x) {
        const float* s = (i < n4) ? s0 : s1;
        __half* d = (i < n4) ? d0 : d1;
        int j = (i < n4) ? i : i - n4;
        float4 v = reinterpret_cast<const float4*>(s)[j];
        reinterpret_cast<uint2*>(d)[j] = make_uint2(pk(v.x, v.y), pk(v.z, v.w));
    }
}

// M1 = scale * Wq1 @ Wk2^T ; M2 = scale * Wq2 @ Wk1^T  (all [256,512] inputs, fp32)
__global__ void compute_M(const float* __restrict__ Wq1, const float* __restrict__ Wk2,
                          const float* __restrict__ Wq2, const float* __restrict__ Wk1,
                          float* __restrict__ Mt) {
    const int d = blockIdx.x, s = blockIdx.y, e = threadIdx.x;
    const float* Wq = s ? Wq2 : Wq1;
    const float* Wk = s ? Wk1 : Wk2;
    __shared__ float4 qrow[128];
    for (int i = threadIdx.x; i < 128; i += 256)
        qrow[i] = reinterpret_cast<const float4*>(Wq + (size_t)d * 512)[i];
    __syncthreads();
    const float4* wk = reinterpret_cast<const float4*>(Wk + (size_t)e * 512);
    float acc = 0.f;
#pragma unroll 8
    for (int i = 0; i < 128; i++) {
        float4 q = qrow[i], w = wk[i];
        acc += q.x * w.x + q.y * w.y + q.z * w.z + q.w * w.w;
    }
    Mt[s * 65536 + d * 256 + e] = acc * 0.0625f;   // scale = 256^-0.5
}

// Pack all GEMM B operands as k-pair fp16x2 words.
// wcomb slice s: [128 kp][768 n]: n<256 -> M_s[k][n]; n>=256 -> Wv_s[k][n-256]
struct PSrc { const float* wv1; const float* wv2; const float* w1; const float* w2; };
__global__ void pack_all(PSrc p, const float* __restrict__ Mt, uint32_t* __restrict__ out) {
    constexpr int RC = 2 * 128 * 768;        // 196608
    constexpr int R1 = RC + 512 * 512;       // 458752
    constexpr int TOT = R1 + 256 * 512;      // 589824
    for (int i = blockIdx.x * blockDim.x + threadIdx.x; i < TOT; i += gridDim.x * blockDim.x) {
        if (i < RC) {
            int s = i / 98304, local = i % 98304;
            int kp = local / 768, n = local % 768;
            float lo, hi;
            if (n < 256) {
                lo = Mt[s * 65536 + (2 * kp) * 256 + n];
                hi = Mt[s * 65536 + (2 * kp + 1) * 256 + n];
            } else {
                const float* Wv = s ? p.wv2 : p.wv1;
                lo = Wv[(size_t)(2 * kp) * 512 + (n - 256)];
                hi = Wv[(size_t)(2 * kp + 1) * 512 + (n - 256)];
            }
            out[i] = pk(lo, hi);
        } else if (i < R1) {
            int j = i - RC; int kp = j >> 9, n = j & 511;
            out[i] = pk(p.w1[(size_t)(2 * kp) * 512 + n], p.w1[(size_t)(2 * kp + 1) * 512 + n]);
        } else {
            int j = i - R1; int kp = j >> 9, n = j & 511;
            out[i] = pk(p.w2[(size_t)(2 * kp) * 512 + n], p.w2[(size_t)(2 * kp + 1) * 512 + n]);
        }
    }
}

// =============================== GEMM =====================================
// C[M,N] = act( alpha * (A @ B) + bias ).  A fp16 row-major [M,K] (lda),
// B pre-packed u32 k-pair words [K/2][N]. 128x128x64 tiles, 3-stage cp.async
// pipeline (prefetch distance 2), 256 thr, 8 warps (4m x 2n).
// ONE barrier per K-tile: iteration t's top barrier is reached by each warp
// only after it finished tile t-1's MMAs, and the load issued in iter t
// targets slot (t-1)%3 — so all consumers of that slot are done first.
constexpr int AW = 36, BW = 136;          // smem strides (words)
constexpr int A_ST = 128 * AW;            // 4608 words
constexpr int B_ST = 32 * BW;             // 4352 words
constexpr int ST_W = A_ST + B_ST;         // 8960 words / stage
constexpr int NST = 3;
constexpr size_t GEMM_SMEM = (size_t)ST_W * NST * 4;   // 107520 B

template<typename TC, bool RELU, bool SPLITA, bool PROJ>
__global__ void __launch_bounds__(256, 2) gemm_p(
    const __half* __restrict__ A0, const __half* __restrict__ A1,
    const uint32_t* __restrict__ Bp, const float* __restrict__ bias,
    TC* __restrict__ C, int K, int ksplit, int lda,
    size_t bstride, size_t cstride, float alpha, int N)
{
    extern __shared__ uint32_t smem[];
    const uint32_t sm_base = (uint32_t)__cvta_generic_to_shared(smem);

    const int tid = threadIdx.x;
    const int bm  = blockIdx.y * 128;
    const int bn  = blockIdx.x * 128;
    const int bz  = blockIdx.z;
    const __half*   Az = PROJ ? (bz ? A1 : A0) : A0;
    const uint32_t* Bz = Bp + (size_t)bz * bstride;
    TC* Cz = C + (size_t)bz * cstride;

    const int w = tid >> 5, lane = tid & 31;
    const int wm = (w & 3) * 32, wn = (w >> 2) * 64;
    const int lr = lane >> 2, lc = lane & 3;

    float acc[2][8][4];
#pragma unroll
    for (int i = 0; i < 2; i++)
#pragma unroll
        for (int j = 0; j < 8; j++)
#pragma unroll
            for (int k = 0; k < 4; k++) acc[i][j][k] = 0.f;

    auto load_stage = [&](int s, int k0) {
        const __half* Ab = Az;
        int kl = k0;
        if (SPLITA && k0 >= ksplit) { Ab = A1; kl = k0 - ksplit; }
        uint32_t abase = sm_base + (uint32_t)(s * ST_W) * 4;
        uint32_t bbase = abase + (uint32_t)A_ST * 4;
#pragma unroll
        for (int i = 0; i < 4; i++) {
            int id = tid + i * 256;
            int r = id >> 3, q = id & 7;
            cpa16(abase + (uint32_t)(r * AW + q * 4) * 4,
                  Ab + (size_t)(bm + r) * lda + kl + q * 8);
        }
#pragma unroll
        for (int i = 0; i < 4; i++) {
            int id = tid + i * 256;
            int kp = id >> 5, j = id & 31;
            cpa16(bbase + (uint32_t)(kp * BW + j * 4) * 4,
                  Bz + (size_t)((k0 >> 1) + kp) * N + bn + j * 4);
        }
    };

    const int nt = K >> 6;
    load_stage(0, 0);  cpa_commit();
    if (nt > 1) load_stage(1, 64);
    cpa_commit();

    for (int t = 0; t < nt; t++) {
        cpa_wait<1>();
        __syncthreads();   // single barrier per tile (see header comment)
        int tn = t + 2;
        if (tn < nt) load_stage(tn % NST, tn << 6);
        cpa_commit();

        const uint32_t* Ast = smem + (t % NST) * ST_W;
        const uint32_t* Bst = Ast + A_ST;
#pragma unroll
        for (int kk2 = 0; kk2 < 32; kk2 += 8) {
            uint32_t af[2][4];
#pragma unroll
            for (int mi = 0; mi < 2; mi++) {
                int r0 = wm + mi * 16 + lr;
                af[mi][0] = Ast[r0 * AW + kk2 + lc];
                af[mi][1] = Ast[(r0 + 8) * AW + kk2 + lc];
                af[mi][2] = Ast[r0 * AW + kk2 + lc + 4];
                af[mi][3] = Ast[(r0 + 8) * AW + kk2 + lc + 4];
            }
            uint32_t bf[8][2];
#pragma unroll
            for (int ni = 0; ni < 8; ni++) {
                int c0 = wn + ni * 8 + lr;
                bf[ni][0] = Bst[(kk2 + lc) * BW + c0];
                bf[ni][1] = Bst[(kk2 + lc + 4) * BW + c0];
            }
#pragma unroll
            for (int mi = 0; mi < 2; mi++)
#pragma unroll
                for (int ni = 0; ni < 8; ni++)
                    mma16v(acc[mi][ni],
                           af[mi][0], af[mi][1], af[mi][2], af[mi][3],
                           bf[ni][0], bf[ni][1]);
        }
    }

    // epilogue
#pragma unroll
    for (int mi = 0; mi < 2; mi++) {
#pragma unroll
        for (int ni = 0; ni < 8; ni++) {
            int row = bm + wm + mi * 16 + lr;
            int col = bn + wn + ni * 8 + lc * 2;
            float b0 = 0.f, b1 = 0.f;
            if (bias) { b0 = bias[col]; b1 = bias[col + 1]; }
            float v0 = acc[mi][ni][0] * alpha + b0;
            float v1 = acc[mi][ni][1] * alpha + b1;
            float v2 = acc[mi][ni][2] * alpha + b0;
            float v3 = acc[mi][ni][3] * alpha + b1;
            if (RELU) {
                v0 = fmaxf(v0, 0.f); v1 = fmaxf(v1, 0.f);
                v2 = fmaxf(v2, 0.f); v3 = fmaxf(v3, 0.f);
            }
            st2(Cz + (size_t)row * N + col, v0, v1);
            st2(Cz + (size_t)(row + 8) * N + col, v2, v3);
        }
    }
}

// ============================ Attention ===================================
// grid (2048, 2).
//   y==0: S = xm1 @ xh2^T (contraction 256), a1 = softmax(S) @ v1
//   y==1: S = xm2 @ xh1^T,                   a2 = softmax(S) @ v2
// Q = slice buffer cols [0,256) stride 768; K = xh stride 256;
// V = O = slice buffer cols [256,768) stride 768 (aliased, chunk-safe).
constexpr int QW = 36, SLD = 68, VW = 72;
constexpr int QST = 64 * QW;   // 2304 words / stage
constexpr size_t ATTN_SMEM = (size_t)6 * QST * 4;   // 55296 B

__global__ void __launch_bounds__(256, 2) attn_kernel(
    __half* __restrict__ buf1, __half* __restrict__ buf2,
    const __half* __restrict__ xh1, const __half* __restrict__ xh2)
{
    extern __shared__ uint32_t asmem[];
    uint32_t* sQ = asmem;            // 3 stages Q; later S (fp32)
    uint32_t* sK = asmem + 3 * QST;  // 3 stages K; later P (stage0) + V (1,2)

    const int tid = threadIdx.x, w = tid >> 5, lane = tid & 31;
    const int lr = lane >> 2, lc = lane & 3;
    const int wm = (w & 3) * 16;
    const int wn = (w >> 2) * 32;

    const __half* Q; const __half* Kx; __half* V;
    if (blockIdx.y == 0) { Q = buf1; Kx = xh2; V = buf1 + 256; }
    else                 { Q = buf2; Kx = xh1; V = buf2 + 256; }
    __half* O = V;
    const size_t qbase = (size_t)blockIdx.x * 64 * 768;
    const size_t kbase = (size_t)blockIdx.x * 64 * 256;

    const uint32_t qsm = (uint32_t)__cvta_generic_to_shared(sQ);
    const uint32_t ksm = (uint32_t)__cvta_generic_to_shared(sK);

    auto loadQK = [&](int st, int hc) {
#pragma unroll
        for (int i = 0; i < 2; i++) {
            int id = tid + i * 256;
            int r = id >> 3, q = id & 7;
            uint32_t off = (uint32_t)(st * QST + r * QW + q * 4) * 4;
            cpa16(qsm + off, Q  + qbase + (size_t)r * 768 + hc + q * 8);
            cpa16(ksm + off, Kx + kbase + (size_t)r * 256 + hc + q * 8);
        }
    };

    float sacc[4][4];
#pragma unroll
    for (int i = 0; i < 4; i++)
#pragma unroll
        for (int j = 0; j < 4; j++) sacc[i][j] = 0.f;

    // ---- Phase 1: S = xm @ xh^T over 256, 4 chunks of 64, pipelined ----
    loadQK(0, 0);   cpa_commit();
    loadQK(1, 64);  cpa_commit();
    for (int c = 0; c < 4; c++) {
        cpa_wait<1>();
        __syncthreads();
        if (c + 2 < 4) loadQK((c + 2) % 3, (c + 2) * 64);
        cpa_commit();

        const uint32_t* qb = sQ + (c % 3) * QST;
        const uint32_t* kb = sK + (c % 3) * QST;
#pragma unroll
        for (int kk2 = 0; kk2 < 32; kk2 += 8) {
            uint32_t af[4];
            int r0 = wm + lr;
            af[0] = qb[r0 * QW + kk2 + lc];
            af[1] = qb[(r0 + 8) * QW + kk2 + lc];
            af[2] = qb[r0 * QW + kk2 + lc + 4];
            af[3] = qb[(r0 + 8) * QW + kk2 + lc + 4];
#pragma unroll
            for (int ni = 0; ni < 4; ni++) {
                int c0 = wn + ni * 8 + lr;
                mma16v(sacc[ni], af[0], af[1], af[2], af[3],
                       kb[c0 * QW + kk2 + lc], kb[c0 * QW + kk2 + lc + 4]);
            }
        }
    }
    __syncthreads();

    // ---- dump S (fp32) into sQ ----
    float* S = reinterpret_cast<float*>(sQ);
#pragma unroll
    for (int ni = 0; ni < 4; ni++) {
        int row = wm + lr, col = wn + ni * 8 + lc * 2;
        S[row * SLD + col]           = sacc[ni][0];
        S[row * SLD + col + 1]       = sacc[ni][1];
        S[(row + 8) * SLD + col]     = sacc[ni][2];
        S[(row + 8) * SLD + col + 1] = sacc[ni][3];
    }
    __syncthreads();

    // ---- Phase 2: softmax (fp32), each warp owns 8 rows ----
    for (int r = w * 8; r < w * 8 + 8; r++) {
        float v0 = S[r * SLD + lane], v1 = S[r * SLD + 32 + lane];
        float m = fmaxf(v0, v1);
#pragma unroll
        for (int o = 16; o > 0; o >>= 1) m = fmaxf(m, __shfl_xor_sync(0xffffffffu, m, o));
        float e0 = __expf(v0 - m), e1 = __expf(v1 - m);
        float s = e0 + e1;
#pragma unroll
        for (int o = 16; o > 0; o >>= 1) s += __shfl_xor_sync(0xffffffffu, s, o);
        float inv = 1.f / s;
        S[r * SLD + lane]      = e0 * inv;
        S[r * SLD + 32 + lane] = e1 * inv;
    }
    __syncthreads();

    // ---- pack P (fp16 pair-words) into sK stage 0 ----
    uint32_t* Pw = sK;
    for (int idx = tid; idx < 64 * 32; idx += 256) {
        int row = idx >> 5, mp = idx & 31;
        Pw[row * QW + mp] = pk(S[row * SLD + 2 * mp], S[row * SLD + 2 * mp + 1]);
    }
    __syncthreads();

    // ---- hoist P fragments (reused for all 8 h-chunks) ----
    uint32_t paf[4][4];
#pragma unroll
    for (int c = 0; c < 4; c++) {
        int kk2 = c * 8, r0 = wm + lr;
        paf[c][0] = Pw[r0 * QW + kk2 + lc];
        paf[c][1] = Pw[(r0 + 8) * QW + kk2 + lc];
        paf[c][2] = Pw[r0 * QW + kk2 + lc + 4];
        paf[c][3] = Pw[(r0 + 8) * QW + kk2 + lc + 4];
    }
    __syncthreads();   // sK free for V stages

    // ---- Phase 3: O = P @ V, reg-pipelined V loads, 2-stage smem ----
    const int mp0 = tid >> 4, h40 = (tid & 15) * 4;
    const int mp1 = (tid + 256) >> 4, h41 = ((tid + 256) & 15) * 4;

    uint2 ra0, rb0, ra1, rb1;
    auto ldV = [&](int hc) {
        ra0 = *reinterpret_cast<const uint2*>(V + qbase + (size_t)(2 * mp0) * 768 + hc + h40);
        rb0 = *reinterpret_cast<const uint2*>(V + qbase + (size_t)(2 * mp0 + 1) * 768 + hc + h40);
        ra1 = *reinterpret_cast<const uint2*>(V + qbase + (size_t)(2 * mp1) * 768 + hc + h41);
        rb1 = *reinterpret_cast<const uint2*>(V + qbase + (size_t)(2 * mp1 + 1) * 768 + hc + h41);
    };
    ldV(0);

    for (int ci = 0; ci < 8; ci++) {
        int hc = ci * 64;
        uint32_t* vb = sK + (1 + (ci & 1)) * QST;   // stages 1,2
        *reinterpret_cast<uint4*>(&vb[mp0 * VW + h40]) =
            make_uint4(__byte_perm(ra0.x, rb0.x, 0x5410), __byte_perm(ra0.x, rb0.x, 0x7632),
                       __byte_perm(ra0.y, rb0.y, 0x5410), __byte_perm(ra0.y, rb0.y, 0x7632));
        *reinterpret_cast<uint4*>(&vb[mp1 * VW + h41]) =
            make_uint4(__byte_perm(ra1.x, rb1.x, 0x5410), __byte_perm(ra1.x, rb1.x, 0x7632),
                       __byte_perm(ra1.y, rb1.y, 0x5410), __byte_perm(ra1.y, rb1.y, 0x7632));
        __syncthreads();

        if (ci + 1 < 8) ldV(hc + 64);  // prefetch next chunk

        float oacc[4][4];
#pragma unroll
        for (int i = 0; i < 4; i++)
#pragma unroll
            for (int j = 0; j < 4; j++) oacc[i][j] = 0.f;
#pragma unroll
        for (int c = 0; c < 4; c++) {
            int kk2 = c * 8;
#pragma unroll
            for (int ni = 0; ni < 4; ni++) {
                int c0 = wn + ni * 8 + lr;
                mma16v(oacc[ni], paf[c][0], paf[c][1], paf[c][2], paf[c][3],
                       vb[(kk2 + lc) * VW + c0], vb[(kk2 + lc + 4) * VW + c0]);
            }
        }
#pragma unroll
        for (int ni = 0; ni < 4; ni++) {
            int row = wm + lr, col = wn + ni * 8 + lc * 2;
            st2(O + qbase + (size_t)row * 768 + hc + col,       oacc[ni][0], oacc[ni][1]);
            st2(O + qbase + (size_t)(row + 8) * 768 + hc + col, oacc[ni][2], oacc[ni][3]);
        }
        __syncthreads();
    }
}

// ============================== launch ====================================
extern "C" void kernel_launch(void* const* d_in, const int* in_sizes, int n_in,
                              void* d_out, int out_size)
{
    const float* x1  = (const float*)d_in[0];
    const float* x2  = (const float*)d_in[1];
    const float* Wq1 = (const float*)d_in[2];
    const float* Wk1 = (const float*)d_in[3];
    const float* Wv1 = (const float*)d_in[4];
    const float* Wq2 = (const float*)d_in[5];
    const float* Wk2 = (const float*)d_in[6];
    const float* Wv2 = (const float*)d_in[7];
    const float* W1  = (const float*)d_in[8];
    const float* b1  = (const float*)d_in[9];
    const float* W2  = (const float*)d_in[10];
    const float* b2  = (const float*)d_in[11];
    float* out = (float*)d_out;

    __half* s;  uint32_t* wbase;  float* mt;
    cudaGetSymbolAddress((void**)&s, g_h);
    cudaGetSymbolAddress((void**)&wbase, g_w);
    cudaGetSymbolAddress((void**)&mt, g_mt);

    __half* buf1 = s;                                 // [M,768]: xm1 | v1/a1
    __half* buf2 = s + (size_t)MROWS * 768;           // [M,768]: xm2 | v2/a2
    __half* xh1  = s + (size_t)MROWS * 1536;          // [M,256]
    __half* xh2  = xh1 + (size_t)MROWS * 256;
    __half* h    = s + (size_t)MROWS * 2048;          // [M,512] MLP hidden

    uint32_t* wcomb = wbase;                          // 2 x (128*768)
    uint32_t* w1p   = wbase + 196608;                 // 512*512
    uint32_t* w2p   = wbase + 458752;                 // 256*512

    dim3 blk(256);

    cudaFuncSetAttribute(gemm_p<__half, false, false, true >, cudaFuncAttributeMaxDynamicSharedMemorySize, (int)GEMM_SMEM);
    cudaFuncSetAttribute(gemm_p<__half, true,  true,  false>, cudaFuncAttributeMaxDynamicSharedMemorySize, (int)GEMM_SMEM);
    cudaFuncSetAttribute(gemm_p<float,  false, false, false>, cudaFuncAttributeMaxDynamicSharedMemorySize, (int)GEMM_SMEM);
    cudaFuncSetAttribute(attn_kernel, cudaFuncAttributeMaxDynamicSharedMemorySize, (int)ATTN_SMEM);

    // ---- pre-pass ----
    cvt_f2h2<<<4096, 256>>>(x1, xh1, x2, xh2, MROWS * 256 / 4);
    compute_M<<<dim3(256, 2), 256>>>(Wq1, Wk2, Wq2, Wk1, mt);
    PSrc ps; ps.wv1 = Wv1; ps.wv2 = Wv2; ps.w1 = W1; ps.w2 = W2;
    pack_all<<<1024, 256>>>(ps, mt, wbase);

    // ---- stage 1: fused [xm | v] projections, 2 slices, N=768 ----
    dim3 gproj(6, MROWS / 128, 2);
    gemm_p<__half, false, false, true><<<gproj, blk, GEMM_SMEM>>>(
        xh1, xh2, wcomb, nullptr, buf1, 256, 0, 256,
        98304, (size_t)MROWS * 768, 1.f, 768);

    // ---- stage 2: both cross attentions ----
    attn_kernel<<<dim3(BT, 2), blk, ATTN_SMEM>>>(buf1, buf2, xh1, xh2);

    // ---- stage 3: MLP ----
    dim3 gmlp(4, MROWS / 128, 1);
    gemm_p<__half, true, true, false><<<gmlp, blk, GEMM_SMEM>>>(
        buf1 + 256, buf2 + 256, w1p, b1, h, 1024, 512, 768, 0, 0, 1.f, 512);
    gemm_p<float, false, false, false><<<gmlp, blk, GEMM_SMEM>>>(
        h, nullptr, w2p, b2, out, 512, 0, 512, 0, 0, 1.f, 512);
}